// round 4
// baseline (speedup 1.0000x reference)
#include <cuda_runtime.h>

#define SEQ_LEN 262144
#define NB4     (SEQ_LEN / 4)   // 65536 float4 chunks
#define HID     256
#define CH      32              // steps per warp in MLP kernel

// Scratch for c_t = B u_t + bA (3 rows, padded for 2-chunk prefetch overrun)
__device__ __align__(16) float g_c0[SEQ_LEN + 8];
__device__ __align__(16) float g_c1[SEQ_LEN + 8];
__device__ __align__(16) float g_c2[SEQ_LEN + 8];

// ---------------------------------------------------------------------------
// Kernel 1: c_t = B @ u_t + bA, fully parallel, float4-vectorized.
// ---------------------------------------------------------------------------
__global__ void precompute_c(const float* __restrict__ u,
                             const float* __restrict__ B,
                             const float* __restrict__ bA) {
    int j = blockIdx.x * blockDim.x + threadIdx.x;   // float4 index
    if (j >= NB4) return;
    const float4* u0 = (const float4*)u;
    const float4* u1 = (const float4*)(u + SEQ_LEN);
    const float4* u2 = (const float4*)(u + 2 * SEQ_LEN);
    float4 a = u0[j], b = u1[j], c = u2[j];

    float B00 = B[0], B01 = B[1], B02 = B[2];
    float B10 = B[3], B11 = B[4], B12 = B[5];
    float B20 = B[6], B21 = B[7], B22 = B[8];
    float A0 = bA[0], A1 = bA[1], A2 = bA[2];

    float4 r0, r1, r2;
    r0.x = fmaf(B00, a.x, fmaf(B01, b.x, fmaf(B02, c.x, A0)));
    r0.y = fmaf(B00, a.y, fmaf(B01, b.y, fmaf(B02, c.y, A0)));
    r0.z = fmaf(B00, a.z, fmaf(B01, b.z, fmaf(B02, c.z, A0)));
    r0.w = fmaf(B00, a.w, fmaf(B01, b.w, fmaf(B02, c.w, A0)));

    r1.x = fmaf(B10, a.x, fmaf(B11, b.x, fmaf(B12, c.x, A1)));
    r1.y = fmaf(B10, a.y, fmaf(B11, b.y, fmaf(B12, c.y, A1)));
    r1.z = fmaf(B10, a.z, fmaf(B11, b.z, fmaf(B12, c.z, A1)));
    r1.w = fmaf(B10, a.w, fmaf(B11, b.w, fmaf(B12, c.w, A1)));

    r2.x = fmaf(B20, a.x, fmaf(B21, b.x, fmaf(B22, c.x, A2)));
    r2.y = fmaf(B20, a.y, fmaf(B21, b.y, fmaf(B22, c.y, A2)));
    r2.z = fmaf(B20, a.z, fmaf(B21, b.z, fmaf(B22, c.z, A2)));
    r2.w = fmaf(B20, a.w, fmaf(B21, b.w, fmaf(B22, c.w, A2)));

    ((float4*)g_c0)[j] = r0;
    ((float4*)g_c1)[j] = r1;
    ((float4*)g_c2)[j] = r2;

    if (j < 2) {   // finite pad for the 2-ahead prefetch in the scan
        float4 z = make_float4(0.f, 0.f, 0.f, 0.f);
        ((float4*)g_c0)[NB4 + j] = z;
        ((float4*)g_c1)[NB4 + j] = z;
        ((float4*)g_c2)[NB4 + j] = z;
    }
}

// ---------------------------------------------------------------------------
// Kernel 2: the strictly serial scan, y-domain formulation.
//   y_{t+1} = (y_t + (c_{t+1}-c_t)) + dtA . tanh(y_t)
//   x_{t+1} = x_t + dt * tanh(y_t)          (membrane output)
// Critical path per step: MUFU.TANH (16, rt 8) + 3-deep FFMA chain ≈ 36 cyc.
// ---------------------------------------------------------------------------
__global__ void __launch_bounds__(32, 1)
seq_scan(const float* __restrict__ Amat,
         const float* __restrict__ dtp,
         float* __restrict__ memb) {
    if (threadIdx.x != 0) return;
    const float dt = dtp[0];
    const float dA00 = dt * Amat[0], dA01 = dt * Amat[1], dA02 = dt * Amat[2];
    const float dA10 = dt * Amat[3], dA11 = dt * Amat[4], dA12 = dt * Amat[5];
    const float dA20 = dt * Amat[6], dA21 = dt * Amat[7], dA22 = dt * Amat[8];

    const float4* C0 = (const float4*)g_c0;
    const float4* C1 = (const float4*)g_c1;
    const float4* C2 = (const float4*)g_c2;
    float4* M0 = (float4*)memb;
    float4* M1 = (float4*)(memb + SEQ_LEN);
    float4* M2 = (float4*)(memb + 2 * SEQ_LEN);

    float4 a0 = C0[0], a1 = C1[0], a2 = C2[0];   // current chunk of c
    float4 b0 = C0[1], b1 = C1[1], b2 = C2[1];   // next chunk
    float y0 = a0.x, y1 = a1.x, y2 = a2.x;       // y_0 = c_0 (x0 = 0)
    float x0 = 0.f, x1 = 0.f, x2 = 0.f;

#define STEP(CN0, CC0, CN1, CC1, CN2, CC2, FLD)                                 \
    do {                                                                        \
        float t0, t1, t2;                                                       \
        asm("tanh.approx.f32 %0, %1;" : "=f"(t0) : "f"(y0));                    \
        asm("tanh.approx.f32 %0, %1;" : "=f"(t1) : "f"(y1));                    \
        asm("tanh.approx.f32 %0, %1;" : "=f"(t2) : "f"(y2));                    \
        float s0 = y0 + (CN0 - CC0);                                            \
        float s1 = y1 + (CN1 - CC1);                                            \
        float s2 = y2 + (CN2 - CC2);                                            \
        x0 = fmaf(dt, t0, x0);                                                  \
        x1 = fmaf(dt, t1, x1);                                                  \
        x2 = fmaf(dt, t2, x2);                                                  \
        o0.FLD = x0; o1.FLD = x1; o2.FLD = x2;                                  \
        y0 = fmaf(dA02, t2, fmaf(dA01, t1, fmaf(dA00, t0, s0)));                \
        y1 = fmaf(dA12, t2, fmaf(dA11, t1, fmaf(dA10, t0, s1)));                \
        y2 = fmaf(dA22, t2, fmaf(dA21, t1, fmaf(dA20, t0, s2)));                \
    } while (0)

    for (int j = 0; j < NB4; ++j) {
        // prefetch chunk j+2 (two ahead => ~288 cycles of cover, L2 hit ~234)
        float4 n0 = C0[j + 2], n1 = C1[j + 2], n2 = C2[j + 2];
        float4 o0, o1, o2;
        STEP(a0.y, a0.x, a1.y, a1.x, a2.y, a2.x, x);
        STEP(a0.z, a0.y, a1.z, a1.y, a2.z, a2.y, y);
        STEP(a0.w, a0.z, a1.w, a1.z, a2.w, a2.z, z);
        STEP(b0.x, a0.w, b1.x, a1.w, b2.x, a2.w, w);
        M0[j] = o0; M1[j] = o1; M2[j] = o2;
        a0 = b0; a1 = b1; a2 = b2;
        b0 = n0; b1 = n1; b2 = n2;
    }
#undef STEP
}

// ---------------------------------------------------------------------------
// Kernel 3: pointwise MLP  out = W2 relu(W1 x + b1) + b2, warp-parallel.
// Lane l owns 8 hidden units (weights in registers); butterfly-reduce 3 sums.
// ---------------------------------------------------------------------------
__global__ void mlp_kernel(const float* __restrict__ memb,
                           const float* __restrict__ W1, const float* __restrict__ b1,
                           const float* __restrict__ W2, const float* __restrict__ b2,
                           float* __restrict__ out) {
    int warp = (blockIdx.x * blockDim.x + threadIdx.x) >> 5;
    int lane = threadIdx.x & 31;
    int tbase = warp * CH;
    if (tbase >= SEQ_LEN) return;

    float w1r[8][3], b1r[8], w2r[3][8];
#pragma unroll
    for (int k = 0; k < 8; ++k) {
        int h = lane * 8 + k;
        w1r[k][0] = W1[h * 3 + 0];
        w1r[k][1] = W1[h * 3 + 1];
        w1r[k][2] = W1[h * 3 + 2];
        b1r[k]    = b1[h];
        w2r[0][k] = W2[0 * HID + h];
        w2r[1][k] = W2[1 * HID + h];
        w2r[2][k] = W2[2 * HID + h];
    }
    float ob0 = b2[0], ob1 = b2[1], ob2 = b2[2];

    for (int t = tbase; t < tbase + CH; ++t) {
        float xv0 = __ldg(&memb[t]);
        float xv1 = __ldg(&memb[SEQ_LEN + t]);
        float xv2 = __ldg(&memb[2 * SEQ_LEN + t]);
        float a0 = 0.f, a1 = 0.f, a2 = 0.f;
#pragma unroll
        for (int k = 0; k < 8; ++k) {
            float hv = fmaf(w1r[k][2], xv2,
                       fmaf(w1r[k][1], xv1,
                       fmaf(w1r[k][0], xv0, b1r[k])));
            hv = fmaxf(hv, 0.f);
            a0 = fmaf(w2r[0][k], hv, a0);
            a1 = fmaf(w2r[1][k], hv, a1);
            a2 = fmaf(w2r[2][k], hv, a2);
        }
#pragma unroll
        for (int off = 16; off > 0; off >>= 1) {
            a0 += __shfl_xor_sync(0xffffffffu, a0, off);
            a1 += __shfl_xor_sync(0xffffffffu, a1, off);
            a2 += __shfl_xor_sync(0xffffffffu, a2, off);
        }
        if (lane == 0) {
            out[t]               = a0 + ob0;
            out[SEQ_LEN + t]     = a1 + ob1;
            out[2 * SEQ_LEN + t] = a2 + ob2;
        }
    }
}

// ---------------------------------------------------------------------------
// Launch: inputs in metadata order: u, dt, A, B, bA, W1, b1, W2, b2.
// d_out layout: outputs[3*S] then membrane_potentials[3*S].
// ---------------------------------------------------------------------------
extern "C" void kernel_launch(void* const* d_in, const int* in_sizes, int n_in,
                              void* d_out, int out_size) {
    const float* u  = (const float*)d_in[0];
    const float* dt = (const float*)d_in[1];
    const float* A  = (const float*)d_in[2];
    const float* B  = (const float*)d_in[3];
    const float* bA = (const float*)d_in[4];
    const float* W1 = (const float*)d_in[5];
    const float* b1 = (const float*)d_in[6];
    const float* W2 = (const float*)d_in[7];
    const float* b2 = (const float*)d_in[8];
    float* out  = (float*)d_out;
    float* memb = out + 3 * SEQ_LEN;

    precompute_c<<<NB4 / 256, 256>>>(u, B, bA);
    seq_scan<<<1, 32>>>(A, dt, memb);
    int warps = SEQ_LEN / CH;                 // 8192 warps
    mlp_kernel<<<warps / 8, 256>>>(memb, W1, b1, W2, b2, out);
}

// round 7
// speedup vs baseline: 7.8008x; 7.8008x over previous
#include <cuda_runtime.h>

#define S_LEN  262144
#define NB4    (S_LEN / 4)       // 65536 float4 chunks
#define K_CH   512               // number of time chunks
#define L_CH   (S_LEN / K_CH)    // 512 steps per chunk
#define LB4    (L_CH / 4)        // 128 float4 iterations per chunk
#define HID    256
#define CHW    32                // timesteps per warp in MLP kernel
#define NSWEEP 8

// c_t = B u_t + bA, and dc_t = c_{t+1} - c_t (dc padded for prefetch overrun)
__device__ __align__(16) float g_c0[S_LEN + 8];
__device__ __align__(16) float g_c1[S_LEN + 8];
__device__ __align__(16) float g_c2[S_LEN + 8];
__device__ __align__(16) float g_dc0[S_LEN + 8];
__device__ __align__(16) float g_dc1[S_LEN + 8];
__device__ __align__(16) float g_dc2[S_LEN + 8];

// Newton-GS sweep state: chunk start guesses, chunk ends, chunk Jacobians
__device__ float g_st[3 * K_CH];
__device__ float g_g [3 * K_CH];
__device__ float g_J [9 * K_CH];

// ---------------------------------------------------------------------------
// Kernel 1: c_t = B @ u_t + bA and dc_t, fully parallel, float4-vectorized.
// ---------------------------------------------------------------------------
__global__ void precompute_c(const float* __restrict__ u,
                             const float* __restrict__ B,
                             const float* __restrict__ bA) {
    int j = blockIdx.x * blockDim.x + threadIdx.x;   // float4 index
    if (j >= NB4) return;
    const float4* u0 = (const float4*)u;
    const float4* u1 = (const float4*)(u + S_LEN);
    const float4* u2 = (const float4*)(u + 2 * S_LEN);
    float4 a = u0[j], b = u1[j], c = u2[j];

    float B00 = B[0], B01 = B[1], B02 = B[2];
    float B10 = B[3], B11 = B[4], B12 = B[5];
    float B20 = B[6], B21 = B[7], B22 = B[8];
    float A0 = bA[0], A1 = bA[1], A2 = bA[2];

    float4 r0, r1, r2;
    r0.x = fmaf(B00, a.x, fmaf(B01, b.x, fmaf(B02, c.x, A0)));
    r0.y = fmaf(B00, a.y, fmaf(B01, b.y, fmaf(B02, c.y, A0)));
    r0.z = fmaf(B00, a.z, fmaf(B01, b.z, fmaf(B02, c.z, A0)));
    r0.w = fmaf(B00, a.w, fmaf(B01, b.w, fmaf(B02, c.w, A0)));

    r1.x = fmaf(B10, a.x, fmaf(B11, b.x, fmaf(B12, c.x, A1)));
    r1.y = fmaf(B10, a.y, fmaf(B11, b.y, fmaf(B12, c.y, A1)));
    r1.z = fmaf(B10, a.z, fmaf(B11, b.z, fmaf(B12, c.z, A1)));
    r1.w = fmaf(B10, a.w, fmaf(B11, b.w, fmaf(B12, c.w, A1)));

    r2.x = fmaf(B20, a.x, fmaf(B21, b.x, fmaf(B22, c.x, A2)));
    r2.y = fmaf(B20, a.y, fmaf(B21, b.y, fmaf(B22, c.y, A2)));
    r2.z = fmaf(B20, a.z, fmaf(B21, b.z, fmaf(B22, c.z, A2)));
    r2.w = fmaf(B20, a.w, fmaf(B21, b.w, fmaf(B22, c.w, A2)));

    ((float4*)g_c0)[j] = r0;
    ((float4*)g_c1)[j] = r1;
    ((float4*)g_c2)[j] = r2;

    // next element's c (t = 4j+4) for the dc of the .w lane
    int t4 = 4 * j + 4;
    float n0 = 0.f, n1 = 0.f, n2 = 0.f;
    bool has_next = (t4 < S_LEN);
    if (has_next) {
        float ux = u[t4], uy = u[S_LEN + t4], uz = u[2 * S_LEN + t4];
        n0 = fmaf(B00, ux, fmaf(B01, uy, fmaf(B02, uz, A0)));
        n1 = fmaf(B10, ux, fmaf(B11, uy, fmaf(B12, uz, A1)));
        n2 = fmaf(B20, ux, fmaf(B21, uy, fmaf(B22, uz, A2)));
    }
    float4 d0, d1, d2;
    d0.x = r0.y - r0.x; d0.y = r0.z - r0.y; d0.z = r0.w - r0.z;
    d1.x = r1.y - r1.x; d1.y = r1.z - r1.y; d1.z = r1.w - r1.z;
    d2.x = r2.y - r2.x; d2.y = r2.z - r2.y; d2.z = r2.w - r2.z;
    d0.w = has_next ? (n0 - r0.w) : 0.f;
    d1.w = has_next ? (n1 - r1.w) : 0.f;
    d2.w = has_next ? (n2 - r2.w) : 0.f;
    ((float4*)g_dc0)[j] = d0;
    ((float4*)g_dc1)[j] = d1;
    ((float4*)g_dc2)[j] = d2;

    if (j < 2) {   // pad for the 2-ahead prefetch in chunk kernels
        float4 z = make_float4(0.f, 0.f, 0.f, 0.f);
        ((float4*)g_dc0)[NB4 + j] = z;
        ((float4*)g_dc1)[NB4 + j] = z;
        ((float4*)g_dc2)[NB4 + j] = z;
    }
}

// ---------------------------------------------------------------------------
// Kernel 2: reset chunk-start guesses to 0 (deterministic across replays).
// ---------------------------------------------------------------------------
__global__ void init_starts() {
    int i = threadIdx.x;
    for (; i < 3 * K_CH; i += blockDim.x) g_st[i] = 0.f;
}

#define TANH3(t0v, t1v, t2v)                                                \
    asm("tanh.approx.f32 %0, %1;" : "=f"(t0v) : "f"(y0));                   \
    asm("tanh.approx.f32 %0, %1;" : "=f"(t1v) : "f"(y1));                   \
    asm("tanh.approx.f32 %0, %1;" : "=f"(t2v) : "f"(y2));

// ---------------------------------------------------------------------------
// Kernel 3: per-chunk integration computing end state g_k and Jacobian J_k.
// State: x (3), y = A x + c (y-domain recurrence keeps the tanh chain short),
// J = dx_end/dx_start via J <- (I + dt D_t A) J,  D_t = diag(1 - t^2).
// ---------------------------------------------------------------------------
__global__ void __launch_bounds__(32, 1)
chunk_gj(const float* __restrict__ Amat, const float* __restrict__ dtp) {
    if (threadIdx.x != 0) return;
    int k = blockIdx.x;
    const float dt = dtp[0];
    const float A00 = Amat[0], A01 = Amat[1], A02 = Amat[2];
    const float A10 = Amat[3], A11 = Amat[4], A12 = Amat[5];
    const float A20 = Amat[6], A21 = Amat[7], A22 = Amat[8];
    const float dA00 = dt * A00, dA01 = dt * A01, dA02 = dt * A02;
    const float dA10 = dt * A10, dA11 = dt * A11, dA12 = dt * A12;
    const float dA20 = dt * A20, dA21 = dt * A21, dA22 = dt * A22;

    float x0 = g_st[3 * k + 0], x1 = g_st[3 * k + 1], x2 = g_st[3 * k + 2];
    int t0i = k * L_CH;
    float y0 = fmaf(A00, x0, fmaf(A01, x1, fmaf(A02, x2, g_c0[t0i])));
    float y1 = fmaf(A10, x0, fmaf(A11, x1, fmaf(A12, x2, g_c1[t0i])));
    float y2 = fmaf(A20, x0, fmaf(A21, x1, fmaf(A22, x2, g_c2[t0i])));

    float J00 = 1.f, J01 = 0.f, J02 = 0.f;
    float J10 = 0.f, J11 = 1.f, J12 = 0.f;
    float J20 = 0.f, J21 = 0.f, J22 = 1.f;

    const float4* D0 = (const float4*)g_dc0 + (t0i >> 2);
    const float4* D1 = (const float4*)g_dc1 + (t0i >> 2);
    const float4* D2 = (const float4*)g_dc2 + (t0i >> 2);
    float4 a0 = D0[0], a1 = D1[0], a2 = D2[0];
    float4 b0 = D0[1], b1 = D1[1], b2 = D2[1];

#define GJ_STEP(DC0, DC1, DC2)                                               \
    do {                                                                     \
        float t0v, t1v, t2v;                                                 \
        TANH3(t0v, t1v, t2v);                                                \
        x0 = fmaf(dt, t0v, x0);                                              \
        x1 = fmaf(dt, t1v, x1);                                              \
        x2 = fmaf(dt, t2v, x2);                                              \
        float m0 = dt * t0v, m1 = dt * t1v, m2 = dt * t2v;                   \
        float v0 = fmaf(-m0, t0v, dt);                                       \
        float v1 = fmaf(-m1, t1v, dt);                                       \
        float v2 = fmaf(-m2, t2v, dt);                                       \
        float P00 = fmaf(A00, J00, fmaf(A01, J10, A02 * J20));               \
        float P01 = fmaf(A00, J01, fmaf(A01, J11, A02 * J21));               \
        float P02 = fmaf(A00, J02, fmaf(A01, J12, A02 * J22));               \
        float P10 = fmaf(A10, J00, fmaf(A11, J10, A12 * J20));               \
        float P11 = fmaf(A10, J01, fmaf(A11, J11, A12 * J21));               \
        float P12 = fmaf(A10, J02, fmaf(A11, J12, A12 * J22));               \
        float P20 = fmaf(A20, J00, fmaf(A21, J10, A22 * J20));               \
        float P21 = fmaf(A20, J01, fmaf(A21, J11, A22 * J21));               \
        float P22 = fmaf(A20, J02, fmaf(A21, J12, A22 * J22));               \
        J00 = fmaf(v0, P00, J00); J01 = fmaf(v0, P01, J01);                  \
        J02 = fmaf(v0, P02, J02);                                            \
        J10 = fmaf(v1, P10, J10); J11 = fmaf(v1, P11, J11);                  \
        J12 = fmaf(v1, P12, J12);                                            \
        J20 = fmaf(v2, P20, J20); J21 = fmaf(v2, P21, J21);                  \
        J22 = fmaf(v2, P22, J22);                                            \
        y0 = fmaf(dA02, t2v, fmaf(dA01, t1v, fmaf(dA00, t0v, y0 + (DC0)))); \
        y1 = fmaf(dA12, t2v, fmaf(dA11, t1v, fmaf(dA10, t0v, y1 + (DC1)))); \
        y2 = fmaf(dA22, t2v, fmaf(dA21, t1v, fmaf(dA20, t0v, y2 + (DC2)))); \
    } while (0)

    for (int j = 0; j < LB4; ++j) {
        float4 n0 = D0[j + 2], n1 = D1[j + 2], n2 = D2[j + 2];
        GJ_STEP(a0.x, a1.x, a2.x);
        GJ_STEP(a0.y, a1.y, a2.y);
        GJ_STEP(a0.z, a1.z, a2.z);
        GJ_STEP(a0.w, a1.w, a2.w);
        a0 = b0; a1 = b1; a2 = b2;
        b0 = n0; b1 = n1; b2 = n2;
    }
#undef GJ_STEP

    g_g[3 * k + 0] = x0; g_g[3 * k + 1] = x1; g_g[3 * k + 2] = x2;
    float* Jp = g_J + 9 * k;
    Jp[0] = J00; Jp[1] = J01; Jp[2] = J02;
    Jp[3] = J10; Jp[4] = J11; Jp[5] = J12;
    Jp[6] = J20; Jp[7] = J21; Jp[8] = J22;
}

// ---------------------------------------------------------------------------
// Kernel 4: sequential combine over K chunks (1 thread).
//   x_k = g_k + J_k (x_{k-1} - st_k);  new start of chunk k := x_{k-1}.
// ---------------------------------------------------------------------------
__global__ void combine() {
    if (threadIdx.x != 0) return;
    float p0 = 0.f, p1 = 0.f, p2 = 0.f;   // end of chunk -1 = start of chunk 0
#pragma unroll 2
    for (int k = 0; k < K_CH; ++k) {
        const float* Jp = g_J + 9 * k;
        float s0 = g_st[3 * k + 0], s1 = g_st[3 * k + 1], s2 = g_st[3 * k + 2];
        float d0 = p0 - s0, d1 = p1 - s1, d2 = p2 - s2;
        g_st[3 * k + 0] = p0; g_st[3 * k + 1] = p1; g_st[3 * k + 2] = p2;
        float e0 = fmaf(Jp[0], d0, fmaf(Jp[1], d1, fmaf(Jp[2], d2, g_g[3 * k + 0])));
        float e1 = fmaf(Jp[3], d0, fmaf(Jp[4], d1, fmaf(Jp[5], d2, g_g[3 * k + 1])));
        float e2 = fmaf(Jp[6], d0, fmaf(Jp[7], d1, fmaf(Jp[8], d2, g_g[3 * k + 2])));
        p0 = e0; p1 = e1; p2 = e2;
    }
}

// ---------------------------------------------------------------------------
// Kernel 5: final trajectory pass from converged starts; writes membranes.
// ---------------------------------------------------------------------------
__global__ void __launch_bounds__(32, 1)
chunk_final(const float* __restrict__ Amat, const float* __restrict__ dtp,
            float* __restrict__ memb) {
    if (threadIdx.x != 0) return;
    int k = blockIdx.x;
    const float dt = dtp[0];
    const float A00 = Amat[0], A01 = Amat[1], A02 = Amat[2];
    const float A10 = Amat[3], A11 = Amat[4], A12 = Amat[5];
    const float A20 = Amat[6], A21 = Amat[7], A22 = Amat[8];
    const float dA00 = dt * A00, dA01 = dt * A01, dA02 = dt * A02;
    const float dA10 = dt * A10, dA11 = dt * A11, dA12 = dt * A12;
    const float dA20 = dt * A20, dA21 = dt * A21, dA22 = dt * A22;

    float x0 = g_st[3 * k + 0], x1 = g_st[3 * k + 1], x2 = g_st[3 * k + 2];
    int t0i = k * L_CH;
    float y0 = fmaf(A00, x0, fmaf(A01, x1, fmaf(A02, x2, g_c0[t0i])));
    float y1 = fmaf(A10, x0, fmaf(A11, x1, fmaf(A12, x2, g_c1[t0i])));
    float y2 = fmaf(A20, x0, fmaf(A21, x1, fmaf(A22, x2, g_c2[t0i])));

    const float4* D0 = (const float4*)g_dc0 + (t0i >> 2);
    const float4* D1 = (const float4*)g_dc1 + (t0i >> 2);
    const float4* D2 = (const float4*)g_dc2 + (t0i >> 2);
    float4* M0 = (float4*)memb + (t0i >> 2);
    float4* M1 = (float4*)(memb + S_LEN) + (t0i >> 2);
    float4* M2 = (float4*)(memb + 2 * S_LEN) + (t0i >> 2);

    float4 a0 = D0[0], a1 = D1[0], a2 = D2[0];
    float4 b0 = D0[1], b1 = D1[1], b2 = D2[1];

#define F_STEP(DC0, DC1, DC2, FLD)                                           \
    do {                                                                     \
        float t0v, t1v, t2v;                                                 \
        TANH3(t0v, t1v, t2v);                                                \
        x0 = fmaf(dt, t0v, x0);                                              \
        x1 = fmaf(dt, t1v, x1);                                              \
        x2 = fmaf(dt, t2v, x2);                                              \
        o0.FLD = x0; o1.FLD = x1; o2.FLD = x2;                               \
        y0 = fmaf(dA02, t2v, fmaf(dA01, t1v, fmaf(dA00, t0v, y0 + (DC0)))); \
        y1 = fmaf(dA12, t2v, fmaf(dA11, t1v, fmaf(dA10, t0v, y1 + (DC1)))); \
        y2 = fmaf(dA22, t2v, fmaf(dA21, t1v, fmaf(dA20, t0v, y2 + (DC2)))); \
    } while (0)

    for (int j = 0; j < LB4; ++j) {
        float4 n0 = D0[j + 2], n1 = D1[j + 2], n2 = D2[j + 2];
        float4 o0, o1, o2;
        F_STEP(a0.x, a1.x, a2.x, x);
        F_STEP(a0.y, a1.y, a2.y, y);
        F_STEP(a0.z, a1.z, a2.z, z);
        F_STEP(a0.w, a1.w, a2.w, w);
        M0[j] = o0; M1[j] = o1; M2[j] = o2;
        a0 = b0; a1 = b1; a2 = b2;
        b0 = n0; b1 = n1; b2 = n2;
    }
#undef F_STEP
}

// ---------------------------------------------------------------------------
// Kernel 6: pointwise MLP  out = W2 relu(W1 x + b1) + b2, warp-parallel.
// ---------------------------------------------------------------------------
__global__ void mlp_kernel(const float* __restrict__ memb,
                           const float* __restrict__ W1, const float* __restrict__ b1,
                           const float* __restrict__ W2, const float* __restrict__ b2,
                           float* __restrict__ out) {
    int warp = (blockIdx.x * blockDim.x + threadIdx.x) >> 5;
    int lane = threadIdx.x & 31;
    int tbase = warp * CHW;
    if (tbase >= S_LEN) return;

    float w1r[8][3], b1r[8], w2r[3][8];
#pragma unroll
    for (int k = 0; k < 8; ++k) {
        int h = lane * 8 + k;
        w1r[k][0] = W1[h * 3 + 0];
        w1r[k][1] = W1[h * 3 + 1];
        w1r[k][2] = W1[h * 3 + 2];
        b1r[k]    = b1[h];
        w2r[0][k] = W2[0 * HID + h];
        w2r[1][k] = W2[1 * HID + h];
        w2r[2][k] = W2[2 * HID + h];
    }
    float ob0 = b2[0], ob1 = b2[1], ob2 = b2[2];

    for (int t = tbase; t < tbase + CHW; ++t) {
        float xv0 = __ldg(&memb[t]);
        float xv1 = __ldg(&memb[S_LEN + t]);
        float xv2 = __ldg(&memb[2 * S_LEN + t]);
        float a0 = 0.f, a1 = 0.f, a2 = 0.f;
#pragma unroll
        for (int k = 0; k < 8; ++k) {
            float hv = fmaf(w1r[k][2], xv2,
                       fmaf(w1r[k][1], xv1,
                       fmaf(w1r[k][0], xv0, b1r[k])));
            hv = fmaxf(hv, 0.f);
            a0 = fmaf(w2r[0][k], hv, a0);
            a1 = fmaf(w2r[1][k], hv, a1);
            a2 = fmaf(w2r[2][k], hv, a2);
        }
#pragma unroll
        for (int off = 16; off > 0; off >>= 1) {
            a0 += __shfl_xor_sync(0xffffffffu, a0, off);
            a1 += __shfl_xor_sync(0xffffffffu, a1, off);
            a2 += __shfl_xor_sync(0xffffffffu, a2, off);
        }
        if (lane == 0) {
            out[t]              = a0 + ob0;
            out[S_LEN + t]      = a1 + ob1;
            out[2 * S_LEN + t]  = a2 + ob2;
        }
    }
}

// ---------------------------------------------------------------------------
// Launch: inputs: u, dt, A, B, bA, W1, b1, W2, b2.
// d_out: outputs[3*S] then membrane_potentials[3*S].
// ---------------------------------------------------------------------------
extern "C" void kernel_launch(void* const* d_in, const int* in_sizes, int n_in,
                              void* d_out, int out_size) {
    const float* u  = (const float*)d_in[0];
    const float* dt = (const float*)d_in[1];
    const float* A  = (const float*)d_in[2];
    const float* B  = (const float*)d_in[3];
    const float* bA = (const float*)d_in[4];
    const float* W1 = (const float*)d_in[5];
    const float* b1 = (const float*)d_in[6];
    const float* W2 = (const float*)d_in[7];
    const float* b2 = (const float*)d_in[8];
    float* out  = (float*)d_out;
    float* memb = out + 3 * S_LEN;

    precompute_c<<<NB4 / 256, 256>>>(u, B, bA);
    init_starts<<<1, 256>>>();
    for (int s = 0; s < NSWEEP; ++s) {
        chunk_gj<<<K_CH, 32>>>(A, dt);
        combine<<<1, 32>>>();
    }
    chunk_final<<<K_CH, 32>>>(A, dt, memb);
    mlp_kernel<<<(S_LEN / CHW) / 8, 256>>>(memb, W1, b1, W2, b2, out);
}

// round 12
// speedup vs baseline: 25.1970x; 3.2301x over previous
#include <cuda_runtime.h>

#define S_LEN  262144
#define NB4    (S_LEN / 4)       // 65536 float4 chunks
#define K_CH   512               // number of time chunks
#define L_CH   (S_LEN / K_CH)    // 512 steps per chunk
#define LB4    (L_CH / 4)        // 128 float4 iterations per chunk
#define HID    256
#define CHW    32                // timesteps per warp in MLP kernel
#define NSWEEP 8                 // full Newton-GS sweeps (J recomputed each sweep)

// c_t = B u_t + bA, and dc_t = c_{t+1} - c_t (dc padded for prefetch overrun)
__device__ __align__(16) float g_c0[S_LEN + 8];
__device__ __align__(16) float g_c1[S_LEN + 8];
__device__ __align__(16) float g_c2[S_LEN + 8];
__device__ __align__(16) float g_dc0[S_LEN + 8];
__device__ __align__(16) float g_dc1[S_LEN + 8];
__device__ __align__(16) float g_dc2[S_LEN + 8];

// Newton-GS sweep state
__device__ __align__(16) float g_st[3 * K_CH];   // chunk start guesses
__device__ __align__(16) float g_gp[3 * K_CH];   // g'_k = g_k - J_k s_k
__device__ __align__(16) float g_J [9 * K_CH];   // chunk Jacobians

// ---------------------------------------------------------------------------
// Kernel 1: c_t = B @ u_t + bA and dc_t, fully parallel, float4-vectorized.
// ---------------------------------------------------------------------------
__global__ void precompute_c(const float* __restrict__ u,
                             const float* __restrict__ B,
                             const float* __restrict__ bA) {
    int j = blockIdx.x * blockDim.x + threadIdx.x;   // float4 index
    if (j >= NB4) return;
    const float4* u0 = (const float4*)u;
    const float4* u1 = (const float4*)(u + S_LEN);
    const float4* u2 = (const float4*)(u + 2 * S_LEN);
    float4 a = u0[j], b = u1[j], c = u2[j];

    float B00 = B[0], B01 = B[1], B02 = B[2];
    float B10 = B[3], B11 = B[4], B12 = B[5];
    float B20 = B[6], B21 = B[7], B22 = B[8];
    float A0 = bA[0], A1 = bA[1], A2 = bA[2];

    float4 r0, r1, r2;
    r0.x = fmaf(B00, a.x, fmaf(B01, b.x, fmaf(B02, c.x, A0)));
    r0.y = fmaf(B00, a.y, fmaf(B01, b.y, fmaf(B02, c.y, A0)));
    r0.z = fmaf(B00, a.z, fmaf(B01, b.z, fmaf(B02, c.z, A0)));
    r0.w = fmaf(B00, a.w, fmaf(B01, b.w, fmaf(B02, c.w, A0)));

    r1.x = fmaf(B10, a.x, fmaf(B11, b.x, fmaf(B12, c.x, A1)));
    r1.y = fmaf(B10, a.y, fmaf(B11, b.y, fmaf(B12, c.y, A1)));
    r1.z = fmaf(B10, a.z, fmaf(B11, b.z, fmaf(B12, c.z, A1)));
    r1.w = fmaf(B10, a.w, fmaf(B11, b.w, fmaf(B12, c.w, A1)));

    r2.x = fmaf(B20, a.x, fmaf(B21, b.x, fmaf(B22, c.x, A2)));
    r2.y = fmaf(B20, a.y, fmaf(B21, b.y, fmaf(B22, c.y, A2)));
    r2.z = fmaf(B20, a.z, fmaf(B21, b.z, fmaf(B22, c.z, A2)));
    r2.w = fmaf(B20, a.w, fmaf(B21, b.w, fmaf(B22, c.w, A2)));

    ((float4*)g_c0)[j] = r0;
    ((float4*)g_c1)[j] = r1;
    ((float4*)g_c2)[j] = r2;

    // next element's c (t = 4j+4) for the dc of the .w lane
    int t4 = 4 * j + 4;
    float n0 = 0.f, n1 = 0.f, n2 = 0.f;
    bool has_next = (t4 < S_LEN);
    if (has_next) {
        float ux = u[t4], uy = u[S_LEN + t4], uz = u[2 * S_LEN + t4];
        n0 = fmaf(B00, ux, fmaf(B01, uy, fmaf(B02, uz, A0)));
        n1 = fmaf(B10, ux, fmaf(B11, uy, fmaf(B12, uz, A1)));
        n2 = fmaf(B20, ux, fmaf(B21, uy, fmaf(B22, uz, A2)));
    }
    float4 d0, d1, d2;
    d0.x = r0.y - r0.x; d0.y = r0.z - r0.y; d0.z = r0.w - r0.z;
    d1.x = r1.y - r1.x; d1.y = r1.z - r1.y; d1.z = r1.w - r1.z;
    d2.x = r2.y - r2.x; d2.y = r2.z - r2.y; d2.z = r2.w - r2.z;
    d0.w = has_next ? (n0 - r0.w) : 0.f;
    d1.w = has_next ? (n1 - r1.w) : 0.f;
    d2.w = has_next ? (n2 - r2.w) : 0.f;
    ((float4*)g_dc0)[j] = d0;
    ((float4*)g_dc1)[j] = d1;
    ((float4*)g_dc2)[j] = d2;

    if (j < 2) {   // pad for the 2-ahead prefetch in chunk kernels
        float4 z = make_float4(0.f, 0.f, 0.f, 0.f);
        ((float4*)g_dc0)[NB4 + j] = z;
        ((float4*)g_dc1)[NB4 + j] = z;
        ((float4*)g_dc2)[NB4 + j] = z;
    }
}

// ---------------------------------------------------------------------------
// Kernel 2: reset chunk-start guesses to 0 (deterministic across replays).
// ---------------------------------------------------------------------------
__global__ void init_starts() {
    for (int i = threadIdx.x; i < 3 * K_CH; i += blockDim.x) g_st[i] = 0.f;
}

#define TANH3(t0v, t1v, t2v)                                                \
    asm("tanh.approx.f32 %0, %1;" : "=f"(t0v) : "f"(y0));                   \
    asm("tanh.approx.f32 %0, %1;" : "=f"(t1v) : "f"(y1));                   \
    asm("tanh.approx.f32 %0, %1;" : "=f"(t2v) : "f"(y2));

// ---------------------------------------------------------------------------
// Kernel 3: per-chunk integration: end state, Jacobian, g'_k = g_k - J_k s_k.
// J <- (I + dt D_t A) J,  D_t = diag(1 - tanh^2). Run EVERY sweep (true
// Newton-GS — numerically identical to the measured 6e-7 configuration).
// ---------------------------------------------------------------------------
__global__ void __launch_bounds__(32, 1)
chunk_gj_full(const float* __restrict__ Amat, const float* __restrict__ dtp) {
    if (threadIdx.x != 0) return;
    int k = blockIdx.x;
    const float dt = dtp[0];
    const float A00 = Amat[0], A01 = Amat[1], A02 = Amat[2];
    const float A10 = Amat[3], A11 = Amat[4], A12 = Amat[5];
    const float A20 = Amat[6], A21 = Amat[7], A22 = Amat[8];
    const float dA00 = dt * A00, dA01 = dt * A01, dA02 = dt * A02;
    const float dA10 = dt * A10, dA11 = dt * A11, dA12 = dt * A12;
    const float dA20 = dt * A20, dA21 = dt * A21, dA22 = dt * A22;

    const float s0 = g_st[3 * k + 0], s1 = g_st[3 * k + 1], s2 = g_st[3 * k + 2];
    float x0 = s0, x1 = s1, x2 = s2;
    int t0i = k * L_CH;
    float y0 = fmaf(A00, x0, fmaf(A01, x1, fmaf(A02, x2, g_c0[t0i])));
    float y1 = fmaf(A10, x0, fmaf(A11, x1, fmaf(A12, x2, g_c1[t0i])));
    float y2 = fmaf(A20, x0, fmaf(A21, x1, fmaf(A22, x2, g_c2[t0i])));

    float J00 = 1.f, J01 = 0.f, J02 = 0.f;
    float J10 = 0.f, J11 = 1.f, J12 = 0.f;
    float J20 = 0.f, J21 = 0.f, J22 = 1.f;

    const float4* D0 = (const float4*)g_dc0 + (t0i >> 2);
    const float4* D1 = (const float4*)g_dc1 + (t0i >> 2);
    const float4* D2 = (const float4*)g_dc2 + (t0i >> 2);
    float4 a0 = D0[0], a1 = D1[0], a2 = D2[0];
    float4 b0 = D0[1], b1 = D1[1], b2 = D2[1];

#define GJ_STEP(DC0, DC1, DC2)                                               \
    do {                                                                     \
        float t0v, t1v, t2v;                                                 \
        TANH3(t0v, t1v, t2v);                                                \
        x0 = fmaf(dt, t0v, x0);                                              \
        x1 = fmaf(dt, t1v, x1);                                              \
        x2 = fmaf(dt, t2v, x2);                                              \
        float m0 = dt * t0v, m1 = dt * t1v, m2 = dt * t2v;                   \
        float v0 = fmaf(-m0, t0v, dt);                                       \
        float v1 = fmaf(-m1, t1v, dt);                                       \
        float v2 = fmaf(-m2, t2v, dt);                                       \
        float P00 = fmaf(A00, J00, fmaf(A01, J10, A02 * J20));               \
        float P01 = fmaf(A00, J01, fmaf(A01, J11, A02 * J21));               \
        float P02 = fmaf(A00, J02, fmaf(A01, J12, A02 * J22));               \
        float P10 = fmaf(A10, J00, fmaf(A11, J10, A12 * J20));               \
        float P11 = fmaf(A10, J01, fmaf(A11, J11, A12 * J21));               \
        float P12 = fmaf(A10, J02, fmaf(A11, J12, A12 * J22));               \
        float P20 = fmaf(A20, J00, fmaf(A21, J10, A22 * J20));               \
        float P21 = fmaf(A20, J01, fmaf(A21, J11, A22 * J21));               \
        float P22 = fmaf(A20, J02, fmaf(A21, J12, A22 * J22));               \
        J00 = fmaf(v0, P00, J00); J01 = fmaf(v0, P01, J01);                  \
        J02 = fmaf(v0, P02, J02);                                            \
        J10 = fmaf(v1, P10, J10); J11 = fmaf(v1, P11, J11);                  \
        J12 = fmaf(v1, P12, J12);                                            \
        J20 = fmaf(v2, P20, J20); J21 = fmaf(v2, P21, J21);                  \
        J22 = fmaf(v2, P22, J22);                                            \
        y0 = fmaf(dA02, t2v, fmaf(dA01, t1v, fmaf(dA00, t0v, y0 + (DC0)))); \
        y1 = fmaf(dA12, t2v, fmaf(dA11, t1v, fmaf(dA10, t0v, y1 + (DC1)))); \
        y2 = fmaf(dA22, t2v, fmaf(dA21, t1v, fmaf(dA20, t0v, y2 + (DC2)))); \
    } while (0)

    for (int j = 0; j < LB4; ++j) {
        float4 n0 = D0[j + 2], n1 = D1[j + 2], n2 = D2[j + 2];
        GJ_STEP(a0.x, a1.x, a2.x);
        GJ_STEP(a0.y, a1.y, a2.y);
        GJ_STEP(a0.z, a1.z, a2.z);
        GJ_STEP(a0.w, a1.w, a2.w);
        a0 = b0; a1 = b1; a2 = b2;
        b0 = n0; b1 = n1; b2 = n2;
    }
#undef GJ_STEP

    // g'_k = g_k - J_k s_k  (combine then does p <- J p + g')
    g_gp[3 * k + 0] = x0 - fmaf(J00, s0, fmaf(J01, s1, J02 * s2));
    g_gp[3 * k + 1] = x1 - fmaf(J10, s0, fmaf(J11, s1, J12 * s2));
    g_gp[3 * k + 2] = x2 - fmaf(J20, s0, fmaf(J21, s1, J22 * s2));
    float* Jp = g_J + 9 * k;
    Jp[0] = J00; Jp[1] = J01; Jp[2] = J02;
    Jp[3] = J10; Jp[4] = J11; Jp[5] = J12;
    Jp[6] = J20; Jp[7] = J21; Jp[8] = J22;
}

// ---------------------------------------------------------------------------
// Kernel 4: sequential combine, SMEM-staged.
//   p_k = g'_k + J_k p_{k-1};  new start of chunk k := p_{k-1}.
// 256 threads stage J/g' coalesced into SMEM; thread 0 runs the 512-long
// affine chain (3-deep FMA + LDS); all threads flush the new starts.
// ---------------------------------------------------------------------------
__global__ void __launch_bounds__(256) combine() {
    __shared__ __align__(16) float sJ[9 * K_CH];   // 18 KB
    __shared__ __align__(16) float sg[3 * K_CH];   // 6 KB
    __shared__ __align__(16) float sp[3 * K_CH];   // 6 KB
    int tid = threadIdx.x;

    const float4* GJ = (const float4*)g_J;
    const float4* GG = (const float4*)g_gp;
    float4* SJ = (float4*)sJ;
    float4* SG = (float4*)sg;
#pragma unroll
    for (int i = tid; i < (9 * K_CH) / 4; i += 256) SJ[i] = GJ[i];
#pragma unroll
    for (int i = tid; i < (3 * K_CH) / 4; i += 256) SG[i] = GG[i];
    __syncthreads();

    if (tid == 0) {
        float p0 = 0.f, p1 = 0.f, p2 = 0.f;
#pragma unroll 4
        for (int k = 0; k < K_CH; ++k) {
            const float* Jk = sJ + 9 * k;
            const float* Gk = sg + 3 * k;
            sp[3 * k + 0] = p0; sp[3 * k + 1] = p1; sp[3 * k + 2] = p2;
            float e0 = fmaf(Jk[0], p0, fmaf(Jk[1], p1, fmaf(Jk[2], p2, Gk[0])));
            float e1 = fmaf(Jk[3], p0, fmaf(Jk[4], p1, fmaf(Jk[5], p2, Gk[1])));
            float e2 = fmaf(Jk[6], p0, fmaf(Jk[7], p1, fmaf(Jk[8], p2, Gk[2])));
            p0 = e0; p1 = e1; p2 = e2;
        }
    }
    __syncthreads();
    float4* ST = (float4*)g_st;
    const float4* SP = (const float4*)sp;
#pragma unroll
    for (int i = tid; i < (3 * K_CH) / 4; i += 256) ST[i] = SP[i];
}

// ---------------------------------------------------------------------------
// Kernel 5: final trajectory pass from converged starts; writes membranes.
// ---------------------------------------------------------------------------
__global__ void __launch_bounds__(32, 1)
chunk_final(const float* __restrict__ Amat, const float* __restrict__ dtp,
            float* __restrict__ memb) {
    if (threadIdx.x != 0) return;
    int k = blockIdx.x;
    const float dt = dtp[0];
    const float A00 = Amat[0], A01 = Amat[1], A02 = Amat[2];
    const float A10 = Amat[3], A11 = Amat[4], A12 = Amat[5];
    const float A20 = Amat[6], A21 = Amat[7], A22 = Amat[8];
    const float dA00 = dt * A00, dA01 = dt * A01, dA02 = dt * A02;
    const float dA10 = dt * A10, dA11 = dt * A11, dA12 = dt * A12;
    const float dA20 = dt * A20, dA21 = dt * A21, dA22 = dt * A22;

    float x0 = g_st[3 * k + 0], x1 = g_st[3 * k + 1], x2 = g_st[3 * k + 2];
    int t0i = k * L_CH;
    float y0 = fmaf(A00, x0, fmaf(A01, x1, fmaf(A02, x2, g_c0[t0i])));
    float y1 = fmaf(A10, x0, fmaf(A11, x1, fmaf(A12, x2, g_c1[t0i])));
    float y2 = fmaf(A20, x0, fmaf(A21, x1, fmaf(A22, x2, g_c2[t0i])));

    const float4* D0 = (const float4*)g_dc0 + (t0i >> 2);
    const float4* D1 = (const float4*)g_dc1 + (t0i >> 2);
    const float4* D2 = (const float4*)g_dc2 + (t0i >> 2);
    float4* M0 = (float4*)memb + (t0i >> 2);
    float4* M1 = (float4*)(memb + S_LEN) + (t0i >> 2);
    float4* M2 = (float4*)(memb + 2 * S_LEN) + (t0i >> 2);

    float4 a0 = D0[0], a1 = D1[0], a2 = D2[0];
    float4 b0 = D0[1], b1 = D1[1], b2 = D2[1];

#define F_STEP(DC0, DC1, DC2, FLD)                                           \
    do {                                                                     \
        float t0v, t1v, t2v;                                                 \
        TANH3(t0v, t1v, t2v);                                                \
        x0 = fmaf(dt, t0v, x0);                                              \
        x1 = fmaf(dt, t1v, x1);                                              \
        x2 = fmaf(dt, t2v, x2);                                              \
        o0.FLD = x0; o1.FLD = x1; o2.FLD = x2;                               \
        y0 = fmaf(dA02, t2v, fmaf(dA01, t1v, fmaf(dA00, t0v, y0 + (DC0)))); \
        y1 = fmaf(dA12, t2v, fmaf(dA11, t1v, fmaf(dA10, t0v, y1 + (DC1)))); \
        y2 = fmaf(dA22, t2v, fmaf(dA21, t1v, fmaf(dA20, t0v, y2 + (DC2)))); \
    } while (0)

    for (int j = 0; j < LB4; ++j) {
        float4 n0 = D0[j + 2], n1 = D1[j + 2], n2 = D2[j + 2];
        float4 o0, o1, o2;
        F_STEP(a0.x, a1.x, a2.x, x);
        F_STEP(a0.y, a1.y, a2.y, y);
        F_STEP(a0.z, a1.z, a2.z, z);
        F_STEP(a0.w, a1.w, a2.w, w);
        M0[j] = o0; M1[j] = o1; M2[j] = o2;
        a0 = b0; a1 = b1; a2 = b2;
        b0 = n0; b1 = n1; b2 = n2;
    }
#undef F_STEP
}

// ---------------------------------------------------------------------------
// Kernel 6: pointwise MLP  out = W2 relu(W1 x + b1) + b2, warp-parallel.
// ---------------------------------------------------------------------------
__global__ void mlp_kernel(const float* __restrict__ memb,
                           const float* __restrict__ W1, const float* __restrict__ b1,
                           const float* __restrict__ W2, const float* __restrict__ b2,
                           float* __restrict__ out) {
    int warp = (blockIdx.x * blockDim.x + threadIdx.x) >> 5;
    int lane = threadIdx.x & 31;
    int tbase = warp * CHW;
    if (tbase >= S_LEN) return;

    float w1r[8][3], b1r[8], w2r[3][8];
#pragma unroll
    for (int k = 0; k < 8; ++k) {
        int h = lane * 8 + k;
        w1r[k][0] = W1[h * 3 + 0];
        w1r[k][1] = W1[h * 3 + 1];
        w1r[k][2] = W1[h * 3 + 2];
        b1r[k]    = b1[h];
        w2r[0][k] = W2[0 * HID + h];
        w2r[1][k] = W2[1 * HID + h];
        w2r[2][k] = W2[2 * HID + h];
    }
    float ob0 = b2[0], ob1 = b2[1], ob2 = b2[2];

    for (int t = tbase; t < tbase + CHW; ++t) {
        float xv0 = __ldg(&memb[t]);
        float xv1 = __ldg(&memb[S_LEN + t]);
        float xv2 = __ldg(&memb[2 * S_LEN + t]);
        float a0 = 0.f, a1 = 0.f, a2 = 0.f;
#pragma unroll
        for (int k = 0; k < 8; ++k) {
            float hv = fmaf(w1r[k][2], xv2,
                       fmaf(w1r[k][1], xv1,
                       fmaf(w1r[k][0], xv0, b1r[k])));
            hv = fmaxf(hv, 0.f);
            a0 = fmaf(w2r[0][k], hv, a0);
            a1 = fmaf(w2r[1][k], hv, a1);
            a2 = fmaf(w2r[2][k], hv, a2);
        }
#pragma unroll
        for (int off = 16; off > 0; off >>= 1) {
            a0 += __shfl_xor_sync(0xffffffffu, a0, off);
            a1 += __shfl_xor_sync(0xffffffffu, a1, off);
            a2 += __shfl_xor_sync(0xffffffffu, a2, off);
        }
        if (lane == 0) {
            out[t]              = a0 + ob0;
            out[S_LEN + t]      = a1 + ob1;
            out[2 * S_LEN + t]  = a2 + ob2;
        }
    }
}

// ---------------------------------------------------------------------------
// Launch: inputs: u, dt, A, B, bA, W1, b1, W2, b2.
// d_out: outputs[3*S] then membrane_potentials[3*S].
// ---------------------------------------------------------------------------
extern "C" void kernel_launch(void* const* d_in, const int* in_sizes, int n_in,
                              void* d_out, int out_size) {
    const float* u  = (const float*)d_in[0];
    const float* dt = (const float*)d_in[1];
    const float* A  = (const float*)d_in[2];
    const float* B  = (const float*)d_in[3];
    const float* bA = (const float*)d_in[4];
    const float* W1 = (const float*)d_in[5];
    const float* b1 = (const float*)d_in[6];
    const float* W2 = (const float*)d_in[7];
    const float* b2 = (const float*)d_in[8];
    float* out  = (float*)d_out;
    float* memb = out + 3 * S_LEN;

    precompute_c<<<NB4 / 256, 256>>>(u, B, bA);
    init_starts<<<1, 256>>>();
    for (int s = 0; s < NSWEEP; ++s) {    // full Newton-GS every sweep
        chunk_gj_full<<<K_CH, 32>>>(A, dt);
        combine<<<1, 256>>>();
    }
    chunk_final<<<K_CH, 32>>>(A, dt, memb);
    mlp_kernel<<<(S_LEN / CHW) / 8, 256>>>(memb, W1, b1, W2, b2, out);
}

// round 13
// speedup vs baseline: 45.0839x; 1.7893x over previous
#include <cuda_runtime.h>

#define S_LEN  262144
#define NB4    (S_LEN / 4)       // 65536 float4 chunks
#define K_CH   512               // number of time chunks
#define L_CH   (S_LEN / K_CH)    // 512 steps per chunk
#define LB4    (L_CH / 4)        // 128 float4 iterations per chunk
#define HID    256
#define CHW    32                // timesteps per warp in MLP kernel
#define NSWEEP 6                 // full Newton-GS sweeps (J recomputed each sweep)

// c_t = B u_t + bA, and dc_t = c_{t+1} - c_t (dc padded for prefetch overrun)
__device__ __align__(16) float g_c0[S_LEN + 8];
__device__ __align__(16) float g_c1[S_LEN + 8];
__device__ __align__(16) float g_c2[S_LEN + 8];
__device__ __align__(16) float g_dc0[S_LEN + 8];
__device__ __align__(16) float g_dc1[S_LEN + 8];
__device__ __align__(16) float g_dc2[S_LEN + 8];

// Newton-GS sweep state
__device__ __align__(16) float g_st[3 * K_CH];   // chunk start guesses
__device__ __align__(16) float g_gp[3 * K_CH];   // g'_k = g_k - J_k s_k
__device__ __align__(16) float g_J [9 * K_CH];   // chunk Jacobians (row-major)

// ---------------------------------------------------------------------------
// Kernel 1: c_t = B @ u_t + bA and dc_t, fully parallel, float4-vectorized.
// ---------------------------------------------------------------------------
__global__ void precompute_c(const float* __restrict__ u,
                             const float* __restrict__ B,
                             const float* __restrict__ bA) {
    int j = blockIdx.x * blockDim.x + threadIdx.x;   // float4 index
    if (j >= NB4) return;
    const float4* u0 = (const float4*)u;
    const float4* u1 = (const float4*)(u + S_LEN);
    const float4* u2 = (const float4*)(u + 2 * S_LEN);
    float4 a = u0[j], b = u1[j], c = u2[j];

    float B00 = B[0], B01 = B[1], B02 = B[2];
    float B10 = B[3], B11 = B[4], B12 = B[5];
    float B20 = B[6], B21 = B[7], B22 = B[8];
    float A0 = bA[0], A1 = bA[1], A2 = bA[2];

    float4 r0, r1, r2;
    r0.x = fmaf(B00, a.x, fmaf(B01, b.x, fmaf(B02, c.x, A0)));
    r0.y = fmaf(B00, a.y, fmaf(B01, b.y, fmaf(B02, c.y, A0)));
    r0.z = fmaf(B00, a.z, fmaf(B01, b.z, fmaf(B02, c.z, A0)));
    r0.w = fmaf(B00, a.w, fmaf(B01, b.w, fmaf(B02, c.w, A0)));

    r1.x = fmaf(B10, a.x, fmaf(B11, b.x, fmaf(B12, c.x, A1)));
    r1.y = fmaf(B10, a.y, fmaf(B11, b.y, fmaf(B12, c.y, A1)));
    r1.z = fmaf(B10, a.z, fmaf(B11, b.z, fmaf(B12, c.z, A1)));
    r1.w = fmaf(B10, a.w, fmaf(B11, b.w, fmaf(B12, c.w, A1)));

    r2.x = fmaf(B20, a.x, fmaf(B21, b.x, fmaf(B22, c.x, A2)));
    r2.y = fmaf(B20, a.y, fmaf(B21, b.y, fmaf(B22, c.y, A2)));
    r2.z = fmaf(B20, a.z, fmaf(B21, b.z, fmaf(B22, c.z, A2)));
    r2.w = fmaf(B20, a.w, fmaf(B21, b.w, fmaf(B22, c.w, A2)));

    ((float4*)g_c0)[j] = r0;
    ((float4*)g_c1)[j] = r1;
    ((float4*)g_c2)[j] = r2;

    // next element's c (t = 4j+4) for the dc of the .w lane
    int t4 = 4 * j + 4;
    float n0 = 0.f, n1 = 0.f, n2 = 0.f;
    bool has_next = (t4 < S_LEN);
    if (has_next) {
        float ux = u[t4], uy = u[S_LEN + t4], uz = u[2 * S_LEN + t4];
        n0 = fmaf(B00, ux, fmaf(B01, uy, fmaf(B02, uz, A0)));
        n1 = fmaf(B10, ux, fmaf(B11, uy, fmaf(B12, uz, A1)));
        n2 = fmaf(B20, ux, fmaf(B21, uy, fmaf(B22, uz, A2)));
    }
    float4 d0, d1, d2;
    d0.x = r0.y - r0.x; d0.y = r0.z - r0.y; d0.z = r0.w - r0.z;
    d1.x = r1.y - r1.x; d1.y = r1.z - r1.y; d1.z = r1.w - r1.z;
    d2.x = r2.y - r2.x; d2.y = r2.z - r2.y; d2.z = r2.w - r2.z;
    d0.w = has_next ? (n0 - r0.w) : 0.f;
    d1.w = has_next ? (n1 - r1.w) : 0.f;
    d2.w = has_next ? (n2 - r2.w) : 0.f;
    ((float4*)g_dc0)[j] = d0;
    ((float4*)g_dc1)[j] = d1;
    ((float4*)g_dc2)[j] = d2;

    if (j < 2) {   // pad for the 2-ahead prefetch in chunk kernels
        float4 z = make_float4(0.f, 0.f, 0.f, 0.f);
        ((float4*)g_dc0)[NB4 + j] = z;
        ((float4*)g_dc1)[NB4 + j] = z;
        ((float4*)g_dc2)[NB4 + j] = z;
    }
}

// ---------------------------------------------------------------------------
// Kernel 2: reset chunk-start guesses to 0 (deterministic across replays).
// ---------------------------------------------------------------------------
__global__ void init_starts() {
    for (int i = threadIdx.x; i < 3 * K_CH; i += blockDim.x) g_st[i] = 0.f;
}

#define TANH3(t0v, t1v, t2v)                                                \
    asm("tanh.approx.f32 %0, %1;" : "=f"(t0v) : "f"(y0));                   \
    asm("tanh.approx.f32 %0, %1;" : "=f"(t1v) : "f"(y1));                   \
    asm("tanh.approx.f32 %0, %1;" : "=f"(t2v) : "f"(y2));

// ---------------------------------------------------------------------------
// Kernel 3: per-chunk integration: end state, Jacobian, g'_k = g_k - J_k s_k.
// J columns split across lanes 0..2 (SIMT: 27-FMA A*J becomes 9 warp instrs).
// x/y/tanh are uniform across the warp (no extra issue cost).
// ---------------------------------------------------------------------------
__global__ void __launch_bounds__(32, 1)
chunk_gj_full(const float* __restrict__ Amat, const float* __restrict__ dtp) {
    int k = blockIdx.x;
    int lane = threadIdx.x;
    const float dt = dtp[0];
    const float A00 = Amat[0], A01 = Amat[1], A02 = Amat[2];
    const float A10 = Amat[3], A11 = Amat[4], A12 = Amat[5];
    const float A20 = Amat[6], A21 = Amat[7], A22 = Amat[8];
    const float dA00 = dt * A00, dA01 = dt * A01, dA02 = dt * A02;
    const float dA10 = dt * A10, dA11 = dt * A11, dA12 = dt * A12;
    const float dA20 = dt * A20, dA21 = dt * A21, dA22 = dt * A22;

    const float s0 = g_st[3 * k + 0], s1 = g_st[3 * k + 1], s2 = g_st[3 * k + 2];
    float x0 = s0, x1 = s1, x2 = s2;
    int t0i = k * L_CH;
    float y0 = fmaf(A00, x0, fmaf(A01, x1, fmaf(A02, x2, g_c0[t0i])));
    float y1 = fmaf(A10, x0, fmaf(A11, x1, fmaf(A12, x2, g_c1[t0i])));
    float y2 = fmaf(A20, x0, fmaf(A21, x1, fmaf(A22, x2, g_c2[t0i])));

    // lane c holds J[:,c]; lanes >= 3 carry a zero column (harmless)
    float Jc0 = (lane == 0) ? 1.f : 0.f;
    float Jc1 = (lane == 1) ? 1.f : 0.f;
    float Jc2 = (lane == 2) ? 1.f : 0.f;

    const float4* D0 = (const float4*)g_dc0 + (t0i >> 2);
    const float4* D1 = (const float4*)g_dc1 + (t0i >> 2);
    const float4* D2 = (const float4*)g_dc2 + (t0i >> 2);
    float4 a0 = D0[0], a1 = D1[0], a2 = D2[0];
    float4 b0 = D0[1], b1 = D1[1], b2 = D2[1];

#define GJ_STEP(DC0, DC1, DC2)                                               \
    do {                                                                     \
        float t0v, t1v, t2v;                                                 \
        TANH3(t0v, t1v, t2v);                                                \
        x0 = fmaf(dt, t0v, x0);                                              \
        x1 = fmaf(dt, t1v, x1);                                              \
        x2 = fmaf(dt, t2v, x2);                                              \
        float m0 = dt * t0v, m1 = dt * t1v, m2 = dt * t2v;                   \
        float v0 = fmaf(-m0, t0v, dt);                                       \
        float v1 = fmaf(-m1, t1v, dt);                                       \
        float v2 = fmaf(-m2, t2v, dt);                                       \
        float P0 = fmaf(A00, Jc0, fmaf(A01, Jc1, A02 * Jc2));                \
        float P1 = fmaf(A10, Jc0, fmaf(A11, Jc1, A12 * Jc2));                \
        float P2 = fmaf(A20, Jc0, fmaf(A21, Jc1, A22 * Jc2));                \
        Jc0 = fmaf(v0, P0, Jc0);                                             \
        Jc1 = fmaf(v1, P1, Jc1);                                             \
        Jc2 = fmaf(v2, P2, Jc2);                                             \
        y0 = fmaf(dA02, t2v, fmaf(dA01, t1v, fmaf(dA00, t0v, y0 + (DC0)))); \
        y1 = fmaf(dA12, t2v, fmaf(dA11, t1v, fmaf(dA10, t0v, y1 + (DC1)))); \
        y2 = fmaf(dA22, t2v, fmaf(dA21, t1v, fmaf(dA20, t0v, y2 + (DC2)))); \
    } while (0)

    for (int j = 0; j < LB4; ++j) {
        float4 n0 = D0[j + 2], n1 = D1[j + 2], n2 = D2[j + 2];
        GJ_STEP(a0.x, a1.x, a2.x);
        GJ_STEP(a0.y, a1.y, a2.y);
        GJ_STEP(a0.z, a1.z, a2.z);
        GJ_STEP(a0.w, a1.w, a2.w);
        a0 = b0; a1 = b1; a2 = b2;
        b0 = n0; b1 = n1; b2 = n2;
    }
#undef GJ_STEP

    // g'_k = x - J s.  lane c contributes J[:,c] * s_c; reduce lanes 0..2.
    float sc = (lane == 0) ? s0 : (lane == 1) ? s1 : (lane == 2) ? s2 : 0.f;
    float r0 = Jc0 * sc, r1 = Jc1 * sc, r2 = Jc2 * sc;
    float q0 = r0 + __shfl_down_sync(0xffffffffu, r0, 1)
                  + __shfl_down_sync(0xffffffffu, r0, 2);
    float q1 = r1 + __shfl_down_sync(0xffffffffu, r1, 1)
                  + __shfl_down_sync(0xffffffffu, r1, 2);
    float q2 = r2 + __shfl_down_sync(0xffffffffu, r2, 1)
                  + __shfl_down_sync(0xffffffffu, r2, 2);
    if (lane == 0) {
        g_gp[3 * k + 0] = x0 - q0;
        g_gp[3 * k + 1] = x1 - q1;
        g_gp[3 * k + 2] = x2 - q2;
    }
    if (lane < 3) {   // lane c stores column c (row-major J)
        float* Jp = g_J + 9 * k;
        Jp[0 + lane] = Jc0;
        Jp[3 + lane] = Jc1;
        Jp[6 + lane] = Jc2;
    }
}

// ---------------------------------------------------------------------------
// Kernel 4: parallel combine — inclusive scan of affine maps (J_k, g'_k)
// under composition. Thread k owns chunk k. Kogge-Stone within warps,
// thread-0 serial scan over the 16 warp totals, then final compose.
// st_k = v-part of inclusive prefix through k-1 applied to 0 (st_0 = 0).
// ---------------------------------------------------------------------------
__global__ void __launch_bounds__(512) combine_scan() {
    int k = threadIdx.x;
    int lane = k & 31, wp = k >> 5;

    const float* Jp = g_J + 9 * k;
    float M00 = Jp[0], M01 = Jp[1], M02 = Jp[2];
    float M10 = Jp[3], M11 = Jp[4], M12 = Jp[5];
    float M20 = Jp[6], M21 = Jp[7], M22 = Jp[8];
    float v0 = g_gp[3 * k + 0], v1 = g_gp[3 * k + 1], v2 = g_gp[3 * k + 2];

    // Kogge-Stone inclusive scan within the warp.
    // self := self ∘ left  (left range applied first): M = Ms*Ml, v = Ms*vl + vs
#pragma unroll
    for (int d = 1; d < 32; d <<= 1) {
        float L00 = __shfl_up_sync(0xffffffffu, M00, d);
        float L01 = __shfl_up_sync(0xffffffffu, M01, d);
        float L02 = __shfl_up_sync(0xffffffffu, M02, d);
        float L10 = __shfl_up_sync(0xffffffffu, M10, d);
        float L11 = __shfl_up_sync(0xffffffffu, M11, d);
        float L12 = __shfl_up_sync(0xffffffffu, M12, d);
        float L20 = __shfl_up_sync(0xffffffffu, M20, d);
        float L21 = __shfl_up_sync(0xffffffffu, M21, d);
        float L22 = __shfl_up_sync(0xffffffffu, M22, d);
        float lv0 = __shfl_up_sync(0xffffffffu, v0, d);
        float lv1 = __shfl_up_sync(0xffffffffu, v1, d);
        float lv2 = __shfl_up_sync(0xffffffffu, v2, d);
        if (lane >= d) {
            float N00 = fmaf(M00, L00, fmaf(M01, L10, M02 * L20));
            float N01 = fmaf(M00, L01, fmaf(M01, L11, M02 * L21));
            float N02 = fmaf(M00, L02, fmaf(M01, L12, M02 * L22));
            float N10 = fmaf(M10, L00, fmaf(M11, L10, M12 * L20));
            float N11 = fmaf(M10, L01, fmaf(M11, L11, M12 * L21));
            float N12 = fmaf(M10, L02, fmaf(M11, L12, M12 * L22));
            float N20 = fmaf(M20, L00, fmaf(M21, L10, M22 * L20));
            float N21 = fmaf(M20, L01, fmaf(M21, L11, M22 * L21));
            float N22 = fmaf(M20, L02, fmaf(M21, L12, M22 * L22));
            float n0  = fmaf(M00, lv0, fmaf(M01, lv1, fmaf(M02, lv2, v0)));
            float n1  = fmaf(M10, lv0, fmaf(M11, lv1, fmaf(M12, lv2, v1)));
            float n2  = fmaf(M20, lv0, fmaf(M21, lv1, fmaf(M22, lv2, v2)));
            M00 = N00; M01 = N01; M02 = N02;
            M10 = N10; M11 = N11; M12 = N12;
            M20 = N20; M21 = N21; M22 = N22;
            v0 = n0; v1 = n1; v2 = n2;
        }
    }

    __shared__ float sT[16][12];            // warp totals
    __shared__ float sE[16][12];            // exclusive warp prefixes
    __shared__ float sv[3 * K_CH];          // inclusive-prefix v per chunk

    if (lane == 31) {
        float* T = sT[wp];
        T[0] = M00; T[1] = M01; T[2] = M02;
        T[3] = M10; T[4] = M11; T[5] = M12;
        T[6] = M20; T[7] = M21; T[8] = M22;
        T[9] = v0;  T[10] = v1; T[11] = v2;
    }
    __syncthreads();

    if (k == 0) {   // serial exclusive scan over 16 warp totals
        float E00 = 1.f, E01 = 0.f, E02 = 0.f;
        float E10 = 0.f, E11 = 1.f, E12 = 0.f;
        float E20 = 0.f, E21 = 0.f, E22 = 1.f;
        float e0 = 0.f, e1 = 0.f, e2 = 0.f;
        for (int w = 0; w < 16; ++w) {
            float* E = sE[w];
            E[0] = E00; E[1] = E01; E[2] = E02;
            E[3] = E10; E[4] = E11; E[5] = E12;
            E[6] = E20; E[7] = E21; E[8] = E22;
            E[9] = e0;  E[10] = e1; E[11] = e2;
            const float* T = sT[w];
            // E := T ∘ E  (E first): M = T*E, v = T*e + tv
            float N00 = fmaf(T[0], E00, fmaf(T[1], E10, T[2] * E20));
            float N01 = fmaf(T[0], E01, fmaf(T[1], E11, T[2] * E21));
            float N02 = fmaf(T[0], E02, fmaf(T[1], E12, T[2] * E22));
            float N10 = fmaf(T[3], E00, fmaf(T[4], E10, T[5] * E20));
            float N11 = fmaf(T[3], E01, fmaf(T[4], E11, T[5] * E21));
            float N12 = fmaf(T[3], E02, fmaf(T[4], E12, T[5] * E22));
            float N20 = fmaf(T[6], E00, fmaf(T[7], E10, T[8] * E20));
            float N21 = fmaf(T[6], E01, fmaf(T[7], E11, T[8] * E21));
            float N22 = fmaf(T[6], E02, fmaf(T[7], E12, T[8] * E22));
            float n0  = fmaf(T[0], e0, fmaf(T[1], e1, fmaf(T[2], e2, T[9])));
            float n1  = fmaf(T[3], e0, fmaf(T[4], e1, fmaf(T[5], e2, T[10])));
            float n2  = fmaf(T[6], e0, fmaf(T[7], e1, fmaf(T[8], e2, T[11])));
            E00 = N00; E01 = N01; E02 = N02;
            E10 = N10; E11 = N11; E12 = N12;
            E20 = N20; E21 = N21; E22 = N22;
            e0 = n0; e1 = n1; e2 = n2;
        }
    }
    __syncthreads();

    // final inclusive v for chunk k: f = M_self * e_warpexcl + v_self
    const float* E = sE[wp];
    float f0 = fmaf(M00, E[9], fmaf(M01, E[10], fmaf(M02, E[11], v0)));
    float f1 = fmaf(M10, E[9], fmaf(M11, E[10], fmaf(M12, E[11], v1)));
    float f2 = fmaf(M20, E[9], fmaf(M21, E[10], fmaf(M22, E[11], v2)));
    sv[3 * k + 0] = f0; sv[3 * k + 1] = f1; sv[3 * k + 2] = f2;
    __syncthreads();

    g_st[3 * k + 0] = k ? sv[3 * k - 3] : 0.f;
    g_st[3 * k + 1] = k ? sv[3 * k - 2] : 0.f;
    g_st[3 * k + 2] = k ? sv[3 * k - 1] : 0.f;
}

// ---------------------------------------------------------------------------
// Kernel 5: final trajectory pass from converged starts; writes membranes.
// ---------------------------------------------------------------------------
__global__ void __launch_bounds__(32, 1)
chunk_final(const float* __restrict__ Amat, const float* __restrict__ dtp,
            float* __restrict__ memb) {
    if (threadIdx.x != 0) return;
    int k = blockIdx.x;
    const float dt = dtp[0];
    const float A00 = Amat[0], A01 = Amat[1], A02 = Amat[2];
    const float A10 = Amat[3], A11 = Amat[4], A12 = Amat[5];
    const float A20 = Amat[6], A21 = Amat[7], A22 = Amat[8];
    const float dA00 = dt * A00, dA01 = dt * A01, dA02 = dt * A02;
    const float dA10 = dt * A10, dA11 = dt * A11, dA12 = dt * A12;
    const float dA20 = dt * A20, dA21 = dt * A21, dA22 = dt * A22;

    float x0 = g_st[3 * k + 0], x1 = g_st[3 * k + 1], x2 = g_st[3 * k + 2];
    int t0i = k * L_CH;
    float y0 = fmaf(A00, x0, fmaf(A01, x1, fmaf(A02, x2, g_c0[t0i])));
    float y1 = fmaf(A10, x0, fmaf(A11, x1, fmaf(A12, x2, g_c1[t0i])));
    float y2 = fmaf(A20, x0, fmaf(A21, x1, fmaf(A22, x2, g_c2[t0i])));

    const float4* D0 = (const float4*)g_dc0 + (t0i >> 2);
    const float4* D1 = (const float4*)g_dc1 + (t0i >> 2);
    const float4* D2 = (const float4*)g_dc2 + (t0i >> 2);
    float4* M0 = (float4*)memb + (t0i >> 2);
    float4* M1 = (float4*)(memb + S_LEN) + (t0i >> 2);
    float4* M2 = (float4*)(memb + 2 * S_LEN) + (t0i >> 2);

    float4 a0 = D0[0], a1 = D1[0], a2 = D2[0];
    float4 b0 = D0[1], b1 = D1[1], b2 = D2[1];

#define F_STEP(DC0, DC1, DC2, FLD)                                           \
    do {                                                                     \
        float t0v, t1v, t2v;                                                 \
        TANH3(t0v, t1v, t2v);                                                \
        x0 = fmaf(dt, t0v, x0);                                              \
        x1 = fmaf(dt, t1v, x1);                                              \
        x2 = fmaf(dt, t2v, x2);                                              \
        o0.FLD = x0; o1.FLD = x1; o2.FLD = x2;                               \
        y0 = fmaf(dA02, t2v, fmaf(dA01, t1v, fmaf(dA00, t0v, y0 + (DC0)))); \
        y1 = fmaf(dA12, t2v, fmaf(dA11, t1v, fmaf(dA10, t0v, y1 + (DC1)))); \
        y2 = fmaf(dA22, t2v, fmaf(dA21, t1v, fmaf(dA20, t0v, y2 + (DC2)))); \
    } while (0)

    for (int j = 0; j < LB4; ++j) {
        float4 n0 = D0[j + 2], n1 = D1[j + 2], n2 = D2[j + 2];
        float4 o0, o1, o2;
        F_STEP(a0.x, a1.x, a2.x, x);
        F_STEP(a0.y, a1.y, a2.y, y);
        F_STEP(a0.z, a1.z, a2.z, z);
        F_STEP(a0.w, a1.w, a2.w, w);
        M0[j] = o0; M1[j] = o1; M2[j] = o2;
        a0 = b0; a1 = b1; a2 = b2;
        b0 = n0; b1 = n1; b2 = n2;
    }
#undef F_STEP
}

// ---------------------------------------------------------------------------
// Kernel 6: pointwise MLP  out = W2 relu(W1 x + b1) + b2, warp-parallel.
// ---------------------------------------------------------------------------
__global__ void mlp_kernel(const float* __restrict__ memb,
                           const float* __restrict__ W1, const float* __restrict__ b1,
                           const float* __restrict__ W2, const float* __restrict__ b2,
                           float* __restrict__ out) {
    int warp = (blockIdx.x * blockDim.x + threadIdx.x) >> 5;
    int lane = threadIdx.x & 31;
    int tbase = warp * CHW;
    if (tbase >= S_LEN) return;

    float w1r[8][3], b1r[8], w2r[3][8];
#pragma unroll
    for (int k = 0; k < 8; ++k) {
        int h = lane * 8 + k;
        w1r[k][0] = W1[h * 3 + 0];
        w1r[k][1] = W1[h * 3 + 1];
        w1r[k][2] = W1[h * 3 + 2];
        b1r[k]    = b1[h];
        w2r[0][k] = W2[0 * HID + h];
        w2r[1][k] = W2[1 * HID + h];
        w2r[2][k] = W2[2 * HID + h];
    }
    float ob0 = b2[0], ob1 = b2[1], ob2 = b2[2];

    for (int t = tbase; t < tbase + CHW; ++t) {
        float xv0 = __ldg(&memb[t]);
        float xv1 = __ldg(&memb[S_LEN + t]);
        float xv2 = __ldg(&memb[2 * S_LEN + t]);
        float a0 = 0.f, a1 = 0.f, a2 = 0.f;
#pragma unroll
        for (int k = 0; k < 8; ++k) {
            float hv = fmaf(w1r[k][2], xv2,
                       fmaf(w1r[k][1], xv1,
                       fmaf(w1r[k][0], xv0, b1r[k])));
            hv = fmaxf(hv, 0.f);
            a0 = fmaf(w2r[0][k], hv, a0);
            a1 = fmaf(w2r[1][k], hv, a1);
            a2 = fmaf(w2r[2][k], hv, a2);
        }
#pragma unroll
        for (int off = 16; off > 0; off >>= 1) {
            a0 += __shfl_xor_sync(0xffffffffu, a0, off);
            a1 += __shfl_xor_sync(0xffffffffu, a1, off);
            a2 += __shfl_xor_sync(0xffffffffu, a2, off);
        }
        if (lane == 0) {
            out[t]              = a0 + ob0;
            out[S_LEN + t]      = a1 + ob1;
            out[2 * S_LEN + t]  = a2 + ob2;
        }
    }
}

// ---------------------------------------------------------------------------
// Launch: inputs: u, dt, A, B, bA, W1, b1, W2, b2.
// d_out: outputs[3*S] then membrane_potentials[3*S].
// ---------------------------------------------------------------------------
extern "C" void kernel_launch(void* const* d_in, const int* in_sizes, int n_in,
                              void* d_out, int out_size) {
    const float* u  = (const float*)d_in[0];
    const float* dt = (const float*)d_in[1];
    const float* A  = (const float*)d_in[2];
    const float* B  = (const float*)d_in[3];
    const float* bA = (const float*)d_in[4];
    const float* W1 = (const float*)d_in[5];
    const float* b1 = (const float*)d_in[6];
    const float* W2 = (const float*)d_in[7];
    const float* b2 = (const float*)d_in[8];
    float* out  = (float*)d_out;
    float* memb = out + 3 * S_LEN;

    precompute_c<<<NB4 / 256, 256>>>(u, B, bA);
    init_starts<<<1, 256>>>();
    for (int s = 0; s < NSWEEP; ++s) {    // full Newton-GS every sweep
        chunk_gj_full<<<K_CH, 32>>>(A, dt);
        combine_scan<<<1, 512>>>();
    }
    chunk_final<<<K_CH, 32>>>(A, dt, memb);
    mlp_kernel<<<(S_LEN / CHW) / 8, 256>>>(memb, W1, b1, W2, b2, out);
}

// round 14
// speedup vs baseline: 53.0082x; 1.1758x over previous
#include <cuda_runtime.h>

#define S_LEN  262144
#define NB4    (S_LEN / 4)       // 65536 float4 chunks
#define K_CH   1024              // number of time chunks
#define L_CH   (S_LEN / K_CH)    // 256 steps per chunk
#define LB4    (L_CH / 4)        // 64 float4 iterations per chunk
#define HID    256
#define CHW    32                // timesteps per warp in MLP kernel
#define NSWEEP 6                 // full Newton-GS sweeps (J recomputed each sweep)

// c_t = B u_t + bA, and dc_t = c_{t+1} - c_t (dc padded for prefetch overrun)
__device__ __align__(16) float g_c0[S_LEN + 8];
__device__ __align__(16) float g_c1[S_LEN + 8];
__device__ __align__(16) float g_c2[S_LEN + 8];
__device__ __align__(16) float g_dc0[S_LEN + 8];
__device__ __align__(16) float g_dc1[S_LEN + 8];
__device__ __align__(16) float g_dc2[S_LEN + 8];

// Newton-GS sweep state
__device__ __align__(16) float g_st[3 * K_CH];   // chunk start guesses
__device__ __align__(16) float g_gp[3 * K_CH];   // g'_k = g_k - J_k s_k
__device__ __align__(16) float g_J [9 * K_CH];   // chunk Jacobians (row-major)

// ---------------------------------------------------------------------------
// Kernel 1: c_t = B @ u_t + bA and dc_t, fully parallel, float4-vectorized.
// Also zeroes the chunk-start guesses (replaces init_starts kernel).
// ---------------------------------------------------------------------------
__global__ void precompute_c(const float* __restrict__ u,
                             const float* __restrict__ B,
                             const float* __restrict__ bA) {
    int j = blockIdx.x * blockDim.x + threadIdx.x;   // float4 index
    if (j >= NB4) return;
    const float4* u0 = (const float4*)u;
    const float4* u1 = (const float4*)(u + S_LEN);
    const float4* u2 = (const float4*)(u + 2 * S_LEN);
    float4 a = u0[j], b = u1[j], c = u2[j];

    float B00 = B[0], B01 = B[1], B02 = B[2];
    float B10 = B[3], B11 = B[4], B12 = B[5];
    float B20 = B[6], B21 = B[7], B22 = B[8];
    float A0 = bA[0], A1 = bA[1], A2 = bA[2];

    float4 r0, r1, r2;
    r0.x = fmaf(B00, a.x, fmaf(B01, b.x, fmaf(B02, c.x, A0)));
    r0.y = fmaf(B00, a.y, fmaf(B01, b.y, fmaf(B02, c.y, A0)));
    r0.z = fmaf(B00, a.z, fmaf(B01, b.z, fmaf(B02, c.z, A0)));
    r0.w = fmaf(B00, a.w, fmaf(B01, b.w, fmaf(B02, c.w, A0)));

    r1.x = fmaf(B10, a.x, fmaf(B11, b.x, fmaf(B12, c.x, A1)));
    r1.y = fmaf(B10, a.y, fmaf(B11, b.y, fmaf(B12, c.y, A1)));
    r1.z = fmaf(B10, a.z, fmaf(B11, b.z, fmaf(B12, c.z, A1)));
    r1.w = fmaf(B10, a.w, fmaf(B11, b.w, fmaf(B12, c.w, A1)));

    r2.x = fmaf(B20, a.x, fmaf(B21, b.x, fmaf(B22, c.x, A2)));
    r2.y = fmaf(B20, a.y, fmaf(B21, b.y, fmaf(B22, c.y, A2)));
    r2.z = fmaf(B20, a.z, fmaf(B21, b.z, fmaf(B22, c.z, A2)));
    r2.w = fmaf(B20, a.w, fmaf(B21, b.w, fmaf(B22, c.w, A2)));

    ((float4*)g_c0)[j] = r0;
    ((float4*)g_c1)[j] = r1;
    ((float4*)g_c2)[j] = r2;

    // next element's c (t = 4j+4) for the dc of the .w lane
    int t4 = 4 * j + 4;
    float n0 = 0.f, n1 = 0.f, n2 = 0.f;
    bool has_next = (t4 < S_LEN);
    if (has_next) {
        float ux = u[t4], uy = u[S_LEN + t4], uz = u[2 * S_LEN + t4];
        n0 = fmaf(B00, ux, fmaf(B01, uy, fmaf(B02, uz, A0)));
        n1 = fmaf(B10, ux, fmaf(B11, uy, fmaf(B12, uz, A1)));
        n2 = fmaf(B20, ux, fmaf(B21, uy, fmaf(B22, uz, A2)));
    }
    float4 d0, d1, d2;
    d0.x = r0.y - r0.x; d0.y = r0.z - r0.y; d0.z = r0.w - r0.z;
    d1.x = r1.y - r1.x; d1.y = r1.z - r1.y; d1.z = r1.w - r1.z;
    d2.x = r2.y - r2.x; d2.y = r2.z - r2.y; d2.z = r2.w - r2.z;
    d0.w = has_next ? (n0 - r0.w) : 0.f;
    d1.w = has_next ? (n1 - r1.w) : 0.f;
    d2.w = has_next ? (n2 - r2.w) : 0.f;
    ((float4*)g_dc0)[j] = d0;
    ((float4*)g_dc1)[j] = d1;
    ((float4*)g_dc2)[j] = d2;

    if (j < 2) {   // pad for the 2-ahead prefetch in chunk kernels
        float4 z = make_float4(0.f, 0.f, 0.f, 0.f);
        ((float4*)g_dc0)[NB4 + j] = z;
        ((float4*)g_dc1)[NB4 + j] = z;
        ((float4*)g_dc2)[NB4 + j] = z;
    }
    if (j < 3 * K_CH) g_st[j] = 0.f;   // init chunk-start guesses
}

#define TANH3(t0v, t1v, t2v)                                                \
    asm("tanh.approx.f32 %0, %1;" : "=f"(t0v) : "f"(y0));                   \
    asm("tanh.approx.f32 %0, %1;" : "=f"(t1v) : "f"(y1));                   \
    asm("tanh.approx.f32 %0, %1;" : "=f"(t2v) : "f"(y2));

// ---------------------------------------------------------------------------
// Kernel 2: per-chunk integration: end state, Jacobian, g'_k = g_k - J_k s_k.
// J columns split across lanes 0..2 (SIMT: 27-FMA A*J becomes 9 warp instrs).
// x/y/tanh are uniform across the warp (no extra issue cost).
// ---------------------------------------------------------------------------
__global__ void __launch_bounds__(32)
chunk_gj_full(const float* __restrict__ Amat, const float* __restrict__ dtp) {
    int k = blockIdx.x;
    int lane = threadIdx.x;
    const float dt = dtp[0];
    const float A00 = Amat[0], A01 = Amat[1], A02 = Amat[2];
    const float A10 = Amat[3], A11 = Amat[4], A12 = Amat[5];
    const float A20 = Amat[6], A21 = Amat[7], A22 = Amat[8];
    const float dA00 = dt * A00, dA01 = dt * A01, dA02 = dt * A02;
    const float dA10 = dt * A10, dA11 = dt * A11, dA12 = dt * A12;
    const float dA20 = dt * A20, dA21 = dt * A21, dA22 = dt * A22;

    const float s0 = g_st[3 * k + 0], s1 = g_st[3 * k + 1], s2 = g_st[3 * k + 2];
    float x0 = s0, x1 = s1, x2 = s2;
    int t0i = k * L_CH;
    float y0 = fmaf(A00, x0, fmaf(A01, x1, fmaf(A02, x2, g_c0[t0i])));
    float y1 = fmaf(A10, x0, fmaf(A11, x1, fmaf(A12, x2, g_c1[t0i])));
    float y2 = fmaf(A20, x0, fmaf(A21, x1, fmaf(A22, x2, g_c2[t0i])));

    // lane c holds J[:,c]; lanes >= 3 carry a zero column (harmless)
    float Jc0 = (lane == 0) ? 1.f : 0.f;
    float Jc1 = (lane == 1) ? 1.f : 0.f;
    float Jc2 = (lane == 2) ? 1.f : 0.f;

    const float4* D0 = (const float4*)g_dc0 + (t0i >> 2);
    const float4* D1 = (const float4*)g_dc1 + (t0i >> 2);
    const float4* D2 = (const float4*)g_dc2 + (t0i >> 2);
    float4 a0 = D0[0], a1 = D1[0], a2 = D2[0];
    float4 b0 = D0[1], b1 = D1[1], b2 = D2[1];

#define GJ_STEP(DC0, DC1, DC2)                                               \
    do {                                                                     \
        float t0v, t1v, t2v;                                                 \
        TANH3(t0v, t1v, t2v);                                                \
        x0 = fmaf(dt, t0v, x0);                                              \
        x1 = fmaf(dt, t1v, x1);                                              \
        x2 = fmaf(dt, t2v, x2);                                              \
        float m0 = dt * t0v, m1 = dt * t1v, m2 = dt * t2v;                   \
        float v0 = fmaf(-m0, t0v, dt);                                       \
        float v1 = fmaf(-m1, t1v, dt);                                       \
        float v2 = fmaf(-m2, t2v, dt);                                       \
        float P0 = fmaf(A00, Jc0, fmaf(A01, Jc1, A02 * Jc2));                \
        float P1 = fmaf(A10, Jc0, fmaf(A11, Jc1, A12 * Jc2));                \
        float P2 = fmaf(A20, Jc0, fmaf(A21, Jc1, A22 * Jc2));                \
        Jc0 = fmaf(v0, P0, Jc0);                                             \
        Jc1 = fmaf(v1, P1, Jc1);                                             \
        Jc2 = fmaf(v2, P2, Jc2);                                             \
        y0 = fmaf(dA02, t2v, fmaf(dA01, t1v, fmaf(dA00, t0v, y0 + (DC0)))); \
        y1 = fmaf(dA12, t2v, fmaf(dA11, t1v, fmaf(dA10, t0v, y1 + (DC1)))); \
        y2 = fmaf(dA22, t2v, fmaf(dA21, t1v, fmaf(dA20, t0v, y2 + (DC2)))); \
    } while (0)

    for (int j = 0; j < LB4; ++j) {
        float4 n0 = D0[j + 2], n1 = D1[j + 2], n2 = D2[j + 2];
        GJ_STEP(a0.x, a1.x, a2.x);
        GJ_STEP(a0.y, a1.y, a2.y);
        GJ_STEP(a0.z, a1.z, a2.z);
        GJ_STEP(a0.w, a1.w, a2.w);
        a0 = b0; a1 = b1; a2 = b2;
        b0 = n0; b1 = n1; b2 = n2;
    }
#undef GJ_STEP

    // g'_k = x - J s.  lane c contributes J[:,c] * s_c; reduce lanes 0..2.
    float sc = (lane == 0) ? s0 : (lane == 1) ? s1 : (lane == 2) ? s2 : 0.f;
    float r0 = Jc0 * sc, r1 = Jc1 * sc, r2 = Jc2 * sc;
    float q0 = r0 + __shfl_down_sync(0xffffffffu, r0, 1)
                  + __shfl_down_sync(0xffffffffu, r0, 2);
    float q1 = r1 + __shfl_down_sync(0xffffffffu, r1, 1)
                  + __shfl_down_sync(0xffffffffu, r1, 2);
    float q2 = r2 + __shfl_down_sync(0xffffffffu, r2, 1)
                  + __shfl_down_sync(0xffffffffu, r2, 2);
    if (lane == 0) {
        g_gp[3 * k + 0] = x0 - q0;
        g_gp[3 * k + 1] = x1 - q1;
        g_gp[3 * k + 2] = x2 - q2;
    }
    if (lane < 3) {   // lane c stores column c (row-major J)
        float* Jp = g_J + 9 * k;
        Jp[0 + lane] = Jc0;
        Jp[3 + lane] = Jc1;
        Jp[6 + lane] = Jc2;
    }
}

// ---------------------------------------------------------------------------
// Kernel 3: parallel combine — inclusive scan of affine maps (J_k, g'_k)
// under composition. Thread k owns chunk k (1024 threads, 32 warps).
// Kogge-Stone within warps, thread-0 serial scan over the 32 warp totals,
// then final compose.  st_k = v-part of prefix through k-1 applied to 0.
// ---------------------------------------------------------------------------
__global__ void __launch_bounds__(K_CH) combine_scan() {
    int k = threadIdx.x;
    int lane = k & 31, wp = k >> 5;

    const float* Jp = g_J + 9 * k;
    float M00 = Jp[0], M01 = Jp[1], M02 = Jp[2];
    float M10 = Jp[3], M11 = Jp[4], M12 = Jp[5];
    float M20 = Jp[6], M21 = Jp[7], M22 = Jp[8];
    float v0 = g_gp[3 * k + 0], v1 = g_gp[3 * k + 1], v2 = g_gp[3 * k + 2];

    // Kogge-Stone inclusive scan within the warp.
    // self := self ∘ left  (left range applied first): M = Ms*Ml, v = Ms*vl + vs
#pragma unroll
    for (int d = 1; d < 32; d <<= 1) {
        float L00 = __shfl_up_sync(0xffffffffu, M00, d);
        float L01 = __shfl_up_sync(0xffffffffu, M01, d);
        float L02 = __shfl_up_sync(0xffffffffu, M02, d);
        float L10 = __shfl_up_sync(0xffffffffu, M10, d);
        float L11 = __shfl_up_sync(0xffffffffu, M11, d);
        float L12 = __shfl_up_sync(0xffffffffu, M12, d);
        float L20 = __shfl_up_sync(0xffffffffu, M20, d);
        float L21 = __shfl_up_sync(0xffffffffu, M21, d);
        float L22 = __shfl_up_sync(0xffffffffu, M22, d);
        float lv0 = __shfl_up_sync(0xffffffffu, v0, d);
        float lv1 = __shfl_up_sync(0xffffffffu, v1, d);
        float lv2 = __shfl_up_sync(0xffffffffu, v2, d);
        if (lane >= d) {
            float N00 = fmaf(M00, L00, fmaf(M01, L10, M02 * L20));
            float N01 = fmaf(M00, L01, fmaf(M01, L11, M02 * L21));
            float N02 = fmaf(M00, L02, fmaf(M01, L12, M02 * L22));
            float N10 = fmaf(M10, L00, fmaf(M11, L10, M12 * L20));
            float N11 = fmaf(M10, L01, fmaf(M11, L11, M12 * L21));
            float N12 = fmaf(M10, L02, fmaf(M11, L12, M12 * L22));
            float N20 = fmaf(M20, L00, fmaf(M21, L10, M22 * L20));
            float N21 = fmaf(M20, L01, fmaf(M21, L11, M22 * L21));
            float N22 = fmaf(M20, L02, fmaf(M21, L12, M22 * L22));
            float n0  = fmaf(M00, lv0, fmaf(M01, lv1, fmaf(M02, lv2, v0)));
            float n1  = fmaf(M10, lv0, fmaf(M11, lv1, fmaf(M12, lv2, v1)));
            float n2  = fmaf(M20, lv0, fmaf(M21, lv1, fmaf(M22, lv2, v2)));
            M00 = N00; M01 = N01; M02 = N02;
            M10 = N10; M11 = N11; M12 = N12;
            M20 = N20; M21 = N21; M22 = N22;
            v0 = n0; v1 = n1; v2 = n2;
        }
    }

    __shared__ float sT[32][12];            // warp totals
    __shared__ float sE[32][12];            // exclusive warp prefixes
    __shared__ float sv[3 * K_CH];          // inclusive-prefix v per chunk

    if (lane == 31) {
        float* T = sT[wp];
        T[0] = M00; T[1] = M01; T[2] = M02;
        T[3] = M10; T[4] = M11; T[5] = M12;
        T[6] = M20; T[7] = M21; T[8] = M22;
        T[9] = v0;  T[10] = v1; T[11] = v2;
    }
    __syncthreads();

    if (k == 0) {   // serial exclusive scan over 32 warp totals
        float E00 = 1.f, E01 = 0.f, E02 = 0.f;
        float E10 = 0.f, E11 = 1.f, E12 = 0.f;
        float E20 = 0.f, E21 = 0.f, E22 = 1.f;
        float e0 = 0.f, e1 = 0.f, e2 = 0.f;
        for (int w = 0; w < 32; ++w) {
            float* E = sE[w];
            E[0] = E00; E[1] = E01; E[2] = E02;
            E[3] = E10; E[4] = E11; E[5] = E12;
            E[6] = E20; E[7] = E21; E[8] = E22;
            E[9] = e0;  E[10] = e1; E[11] = e2;
            const float* T = sT[w];
            // E := T ∘ E  (E first): M = T*E, v = T*e + tv
            float N00 = fmaf(T[0], E00, fmaf(T[1], E10, T[2] * E20));
            float N01 = fmaf(T[0], E01, fmaf(T[1], E11, T[2] * E21));
            float N02 = fmaf(T[0], E02, fmaf(T[1], E12, T[2] * E22));
            float N10 = fmaf(T[3], E00, fmaf(T[4], E10, T[5] * E20));
            float N11 = fmaf(T[3], E01, fmaf(T[4], E11, T[5] * E21));
            float N12 = fmaf(T[3], E02, fmaf(T[4], E12, T[5] * E22));
            float N20 = fmaf(T[6], E00, fmaf(T[7], E10, T[8] * E20));
            float N21 = fmaf(T[6], E01, fmaf(T[7], E11, T[8] * E21));
            float N22 = fmaf(T[6], E02, fmaf(T[7], E12, T[8] * E22));
            float n0  = fmaf(T[0], e0, fmaf(T[1], e1, fmaf(T[2], e2, T[9])));
            float n1  = fmaf(T[3], e0, fmaf(T[4], e1, fmaf(T[5], e2, T[10])));
            float n2  = fmaf(T[6], e0, fmaf(T[7], e1, fmaf(T[8], e2, T[11])));
            E00 = N00; E01 = N01; E02 = N02;
            E10 = N10; E11 = N11; E12 = N12;
            E20 = N20; E21 = N21; E22 = N22;
            e0 = n0; e1 = n1; e2 = n2;
        }
    }
    __syncthreads();

    // final inclusive v for chunk k: f = M_self * e_warpexcl + v_self
    const float* E = sE[wp];
    float f0 = fmaf(M00, E[9], fmaf(M01, E[10], fmaf(M02, E[11], v0)));
    float f1 = fmaf(M10, E[9], fmaf(M11, E[10], fmaf(M12, E[11], v1)));
    float f2 = fmaf(M20, E[9], fmaf(M21, E[10], fmaf(M22, E[11], v2)));
    sv[3 * k + 0] = f0; sv[3 * k + 1] = f1; sv[3 * k + 2] = f2;
    __syncthreads();

    g_st[3 * k + 0] = k ? sv[3 * k - 3] : 0.f;
    g_st[3 * k + 1] = k ? sv[3 * k - 2] : 0.f;
    g_st[3 * k + 2] = k ? sv[3 * k - 1] : 0.f;
}

// ---------------------------------------------------------------------------
// Kernel 4: final trajectory pass from converged starts; writes membranes.
// ---------------------------------------------------------------------------
__global__ void __launch_bounds__(32)
chunk_final(const float* __restrict__ Amat, const float* __restrict__ dtp,
            float* __restrict__ memb) {
    if (threadIdx.x != 0) return;
    int k = blockIdx.x;
    const float dt = dtp[0];
    const float A00 = Amat[0], A01 = Amat[1], A02 = Amat[2];
    const float A10 = Amat[3], A11 = Amat[4], A12 = Amat[5];
    const float A20 = Amat[6], A21 = Amat[7], A22 = Amat[8];
    const float dA00 = dt * A00, dA01 = dt * A01, dA02 = dt * A02;
    const float dA10 = dt * A10, dA11 = dt * A11, dA12 = dt * A12;
    const float dA20 = dt * A20, dA21 = dt * A21, dA22 = dt * A22;

    float x0 = g_st[3 * k + 0], x1 = g_st[3 * k + 1], x2 = g_st[3 * k + 2];
    int t0i = k * L_CH;
    float y0 = fmaf(A00, x0, fmaf(A01, x1, fmaf(A02, x2, g_c0[t0i])));
    float y1 = fmaf(A10, x0, fmaf(A11, x1, fmaf(A12, x2, g_c1[t0i])));
    float y2 = fmaf(A20, x0, fmaf(A21, x1, fmaf(A22, x2, g_c2[t0i])));

    const float4* D0 = (const float4*)g_dc0 + (t0i >> 2);
    const float4* D1 = (const float4*)g_dc1 + (t0i >> 2);
    const float4* D2 = (const float4*)g_dc2 + (t0i >> 2);
    float4* M0 = (float4*)memb + (t0i >> 2);
    float4* M1 = (float4*)(memb + S_LEN) + (t0i >> 2);
    float4* M2 = (float4*)(memb + 2 * S_LEN) + (t0i >> 2);

    float4 a0 = D0[0], a1 = D1[0], a2 = D2[0];
    float4 b0 = D0[1], b1 = D1[1], b2 = D2[1];

#define F_STEP(DC0, DC1, DC2, FLD)                                           \
    do {                                                                     \
        float t0v, t1v, t2v;                                                 \
        TANH3(t0v, t1v, t2v);                                                \
        x0 = fmaf(dt, t0v, x0);                                              \
        x1 = fmaf(dt, t1v, x1);                                              \
        x2 = fmaf(dt, t2v, x2);                                              \
        o0.FLD = x0; o1.FLD = x1; o2.FLD = x2;                               \
        y0 = fmaf(dA02, t2v, fmaf(dA01, t1v, fmaf(dA00, t0v, y0 + (DC0)))); \
        y1 = fmaf(dA12, t2v, fmaf(dA11, t1v, fmaf(dA10, t0v, y1 + (DC1)))); \
        y2 = fmaf(dA22, t2v, fmaf(dA21, t1v, fmaf(dA20, t0v, y2 + (DC2)))); \
    } while (0)

    for (int j = 0; j < LB4; ++j) {
        float4 n0 = D0[j + 2], n1 = D1[j + 2], n2 = D2[j + 2];
        float4 o0, o1, o2;
        F_STEP(a0.x, a1.x, a2.x, x);
        F_STEP(a0.y, a1.y, a2.y, y);
        F_STEP(a0.z, a1.z, a2.z, z);
        F_STEP(a0.w, a1.w, a2.w, w);
        M0[j] = o0; M1[j] = o1; M2[j] = o2;
        a0 = b0; a1 = b1; a2 = b2;
        b0 = n0; b1 = n1; b2 = n2;
    }
#undef F_STEP
}

// ---------------------------------------------------------------------------
// Kernel 5: pointwise MLP  out = W2 relu(W1 x + b1) + b2, warp-parallel.
// ---------------------------------------------------------------------------
__global__ void mlp_kernel(const float* __restrict__ memb,
                           const float* __restrict__ W1, const float* __restrict__ b1,
                           const float* __restrict__ W2, const float* __restrict__ b2,
                           float* __restrict__ out) {
    int warp = (blockIdx.x * blockDim.x + threadIdx.x) >> 5;
    int lane = threadIdx.x & 31;
    int tbase = warp * CHW;
    if (tbase >= S_LEN) return;

    float w1r[8][3], b1r[8], w2r[3][8];
#pragma unroll
    for (int k = 0; k < 8; ++k) {
        int h = lane * 8 + k;
        w1r[k][0] = W1[h * 3 + 0];
        w1r[k][1] = W1[h * 3 + 1];
        w1r[k][2] = W1[h * 3 + 2];
        b1r[k]    = b1[h];
        w2r[0][k] = W2[0 * HID + h];
        w2r[1][k] = W2[1 * HID + h];
        w2r[2][k] = W2[2 * HID + h];
    }
    float ob0 = b2[0], ob1 = b2[1], ob2 = b2[2];

    for (int t = tbase; t < tbase + CHW; ++t) {
        float xv0 = __ldg(&memb[t]);
        float xv1 = __ldg(&memb[S_LEN + t]);
        float xv2 = __ldg(&memb[2 * S_LEN + t]);
        float a0 = 0.f, a1 = 0.f, a2 = 0.f;
#pragma unroll
        for (int k = 0; k < 8; ++k) {
            float hv = fmaf(w1r[k][2], xv2,
                       fmaf(w1r[k][1], xv1,
                       fmaf(w1r[k][0], xv0, b1r[k])));
            hv = fmaxf(hv, 0.f);
            a0 = fmaf(w2r[0][k], hv, a0);
            a1 = fmaf(w2r[1][k], hv, a1);
            a2 = fmaf(w2r[2][k], hv, a2);
        }
#pragma unroll
        for (int off = 16; off > 0; off >>= 1) {
            a0 += __shfl_xor_sync(0xffffffffu, a0, off);
            a1 += __shfl_xor_sync(0xffffffffu, a1, off);
            a2 += __shfl_xor_sync(0xffffffffu, a2, off);
        }
        if (lane == 0) {
            out[t]              = a0 + ob0;
            out[S_LEN + t]      = a1 + ob1;
            out[2 * S_LEN + t]  = a2 + ob2;
        }
    }
}

// ---------------------------------------------------------------------------
// Launch: inputs: u, dt, A, B, bA, W1, b1, W2, b2.
// d_out: outputs[3*S] then membrane_potentials[3*S].
// ---------------------------------------------------------------------------
extern "C" void kernel_launch(void* const* d_in, const int* in_sizes, int n_in,
                              void* d_out, int out_size) {
    const float* u  = (const float*)d_in[0];
    const float* dt = (const float*)d_in[1];
    const float* A  = (const float*)d_in[2];
    const float* B  = (const float*)d_in[3];
    const float* bA = (const float*)d_in[4];
    const float* W1 = (const float*)d_in[5];
    const float* b1 = (const float*)d_in[6];
    const float* W2 = (const float*)d_in[7];
    const float* b2 = (const float*)d_in[8];
    float* out  = (float*)d_out;
    float* memb = out + 3 * S_LEN;

    precompute_c<<<NB4 / 256, 256>>>(u, B, bA);
    for (int s = 0; s < NSWEEP; ++s) {    // full Newton-GS every sweep
        chunk_gj_full<<<K_CH, 32>>>(A, dt);
        combine_scan<<<1, K_CH>>>();
    }
    chunk_final<<<K_CH, 32>>>(A, dt, memb);
    mlp_kernel<<<(S_LEN / CHW) / 8, 256>>>(memb, W1, b1, W2, b2, out);
}

// round 16
// speedup vs baseline: 89.6273x; 1.6908x over previous
#include <cuda_runtime.h>

#define S_LEN  262144
#define NB4    (S_LEN / 4)       // 65536 float4 time-chunks
#define K_CH   4096              // number of time chunks
#define L_CH   (S_LEN / K_CH)    // 64 steps per chunk
#define LB4    (L_CH / 4)        // 16 float4 iterations per chunk (final pass)
#define NWARP  (K_CH / 32)       // 128 warps, one per sweep block
#define HID    256
#define CHW    32                // timesteps per warp in MLP kernel
#define NSWEEP 6                 // full Newton-GS sweeps

// c_t = B u_t + bA: time-major (for final pass) + chunk-major float4 (for sweeps)
__device__ __align__(16) float  g_c0[S_LEN + 8];
__device__ __align__(16) float  g_c1[S_LEN + 8];
__device__ __align__(16) float  g_c2[S_LEN + 8];
__device__ __align__(16) float4 g_cT[S_LEN];          // [s*K_CH + k] = (c0,c1,c2,0)

// Ping-pong affine-map state: per-chunk within-warp inclusive prefixes P and
// per-warp totals T. 12 floats per record: M00..M22 row-major, v0..v2.
__device__ __align__(16) float g_Pb[2][12 * K_CH];
__device__ __align__(16) float g_Tb[2][12 * NWARP];

// ---------------------------------------------------------------------------
// Affine map helpers (3x3 matrix + vector), all in registers.
// ---------------------------------------------------------------------------
struct Map {
    float M00, M01, M02, M10, M11, M12, M20, M21, M22, v0, v1, v2;
};

__device__ __forceinline__ Map map_identity() {
    Map r;
    r.M00 = 1.f; r.M01 = 0.f; r.M02 = 0.f;
    r.M10 = 0.f; r.M11 = 1.f; r.M12 = 0.f;
    r.M20 = 0.f; r.M21 = 0.f; r.M22 = 1.f;
    r.v0 = 0.f; r.v1 = 0.f; r.v2 = 0.f;
    return r;
}

// (s ∘ l): apply l first, then s.  M = Ms*Ml,  v = Ms*vl + vs
__device__ __forceinline__ Map map_comp(const Map& s, const Map& l) {
    Map r;
    r.M00 = fmaf(s.M00, l.M00, fmaf(s.M01, l.M10, s.M02 * l.M20));
    r.M01 = fmaf(s.M00, l.M01, fmaf(s.M01, l.M11, s.M02 * l.M21));
    r.M02 = fmaf(s.M00, l.M02, fmaf(s.M01, l.M12, s.M02 * l.M22));
    r.M10 = fmaf(s.M10, l.M00, fmaf(s.M11, l.M10, s.M12 * l.M20));
    r.M11 = fmaf(s.M10, l.M01, fmaf(s.M11, l.M11, s.M12 * l.M21));
    r.M12 = fmaf(s.M10, l.M02, fmaf(s.M11, l.M12, s.M12 * l.M22));
    r.M20 = fmaf(s.M20, l.M00, fmaf(s.M21, l.M10, s.M22 * l.M20));
    r.M21 = fmaf(s.M20, l.M01, fmaf(s.M21, l.M11, s.M22 * l.M21));
    r.M22 = fmaf(s.M20, l.M02, fmaf(s.M21, l.M12, s.M22 * l.M22));
    r.v0  = fmaf(s.M00, l.v0, fmaf(s.M01, l.v1, fmaf(s.M02, l.v2, s.v0)));
    r.v1  = fmaf(s.M10, l.v0, fmaf(s.M11, l.v1, fmaf(s.M12, l.v2, s.v1)));
    r.v2  = fmaf(s.M20, l.v0, fmaf(s.M21, l.v1, fmaf(s.M22, l.v2, s.v2)));
    return r;
}

__device__ __forceinline__ Map map_shfl_up(const Map& m, int d) {
    Map r;
    r.M00 = __shfl_up_sync(0xffffffffu, m.M00, d);
    r.M01 = __shfl_up_sync(0xffffffffu, m.M01, d);
    r.M02 = __shfl_up_sync(0xffffffffu, m.M02, d);
    r.M10 = __shfl_up_sync(0xffffffffu, m.M10, d);
    r.M11 = __shfl_up_sync(0xffffffffu, m.M11, d);
    r.M12 = __shfl_up_sync(0xffffffffu, m.M12, d);
    r.M20 = __shfl_up_sync(0xffffffffu, m.M20, d);
    r.M21 = __shfl_up_sync(0xffffffffu, m.M21, d);
    r.M22 = __shfl_up_sync(0xffffffffu, m.M22, d);
    r.v0  = __shfl_up_sync(0xffffffffu, m.v0, d);
    r.v1  = __shfl_up_sync(0xffffffffu, m.v1, d);
    r.v2  = __shfl_up_sync(0xffffffffu, m.v2, d);
    return r;
}

__device__ __forceinline__ Map map_load(const float* p) {
    const float4* q = (const float4*)p;
    float4 a = q[0], b = q[1], c = q[2];
    Map r;
    r.M00 = a.x; r.M01 = a.y; r.M02 = a.z; r.M10 = a.w;
    r.M11 = b.x; r.M12 = b.y; r.M20 = b.z; r.M21 = b.w;
    r.M22 = c.x; r.v0 = c.y; r.v1 = c.z; r.v2 = c.w;
    return r;
}

__device__ __forceinline__ void map_store(float* p, const Map& m) {
    float4* q = (float4*)p;
    q[0] = make_float4(m.M00, m.M01, m.M02, m.M10);
    q[1] = make_float4(m.M11, m.M12, m.M20, m.M21);
    q[2] = make_float4(m.M22, m.v0, m.v1, m.v2);
}

// Warp-collective: e = (compose of totals T_0..T_{w-1}, in order)(0).
// Lanes load 4 totals each (coalesced), predicate-compose, KS-scan, bcast.
__device__ __forceinline__ void warp_excl_total(const float* Tr, int w, int lane,
                                                float& e0, float& e1, float& e2) {
    Map C = map_identity();
#pragma unroll
    for (int i = 0; i < 4; ++i) {
        int j = (lane << 2) + i;
        Map T = map_load(Tr + 12 * j);
        if (j < w) C = map_comp(T, C);
    }
#pragma unroll
    for (int d = 1; d < 32; d <<= 1) {
        Map L = map_shfl_up(C, d);
        if (lane >= d) C = map_comp(C, L);
    }
    e0 = __shfl_sync(0xffffffffu, C.v0, 31);
    e1 = __shfl_sync(0xffffffffu, C.v1, 31);
    e2 = __shfl_sync(0xffffffffu, C.v2, 31);
}

// ---------------------------------------------------------------------------
// Kernel 1: c_t = B @ u_t + bA: time-major float arrays + chunk-major float4.
// ---------------------------------------------------------------------------
__global__ void precompute_c(const float* __restrict__ u,
                             const float* __restrict__ B,
                             const float* __restrict__ bA) {
    int j = blockIdx.x * blockDim.x + threadIdx.x;   // float4 time index
    if (j >= NB4) return;
    const float4* u0 = (const float4*)u;
    const float4* u1 = (const float4*)(u + S_LEN);
    const float4* u2 = (const float4*)(u + 2 * S_LEN);
    float4 a = u0[j], b = u1[j], c = u2[j];

    float B00 = B[0], B01 = B[1], B02 = B[2];
    float B10 = B[3], B11 = B[4], B12 = B[5];
    float B20 = B[6], B21 = B[7], B22 = B[8];
    float A0 = bA[0], A1 = bA[1], A2 = bA[2];

    float4 r0, r1, r2;
    r0.x = fmaf(B00, a.x, fmaf(B01, b.x, fmaf(B02, c.x, A0)));
    r0.y = fmaf(B00, a.y, fmaf(B01, b.y, fmaf(B02, c.y, A0)));
    r0.z = fmaf(B00, a.z, fmaf(B01, b.z, fmaf(B02, c.z, A0)));
    r0.w = fmaf(B00, a.w, fmaf(B01, b.w, fmaf(B02, c.w, A0)));

    r1.x = fmaf(B10, a.x, fmaf(B11, b.x, fmaf(B12, c.x, A1)));
    r1.y = fmaf(B10, a.y, fmaf(B11, b.y, fmaf(B12, c.y, A1)));
    r1.z = fmaf(B10, a.z, fmaf(B11, b.z, fmaf(B12, c.z, A1)));
    r1.w = fmaf(B10, a.w, fmaf(B11, b.w, fmaf(B12, c.w, A1)));

    r2.x = fmaf(B20, a.x, fmaf(B21, b.x, fmaf(B22, c.x, A2)));
    r2.y = fmaf(B20, a.y, fmaf(B21, b.y, fmaf(B22, c.y, A2)));
    r2.z = fmaf(B20, a.z, fmaf(B21, b.z, fmaf(B22, c.z, A2)));
    r2.w = fmaf(B20, a.w, fmaf(B21, b.w, fmaf(B22, c.w, A2)));

    ((float4*)g_c0)[j] = r0;
    ((float4*)g_c1)[j] = r1;
    ((float4*)g_c2)[j] = r2;

    // chunk-major transpose: t = 4j..4j+3, all in same chunk (64 | alignment)
    int t = 4 * j;
    int k = t >> 6;        // chunk index (L_CH = 64)
    int s = t & 63;        // step within chunk
    g_cT[(s + 0) * K_CH + k] = make_float4(r0.x, r1.x, r2.x, 0.f);
    g_cT[(s + 1) * K_CH + k] = make_float4(r0.y, r1.y, r2.y, 0.f);
    g_cT[(s + 2) * K_CH + k] = make_float4(r0.z, r1.z, r2.z, 0.f);
    g_cT[(s + 3) * K_CH + k] = make_float4(r0.w, r1.w, r2.w, 0.f);

    if (j < 2) {   // pad for the final pass's float4 prefetch overrun
        float4 z = make_float4(0.f, 0.f, 0.f, 0.f);
        ((float4*)g_c0)[NB4 + j] = z;
        ((float4*)g_c1)[NB4 + j] = z;
        ((float4*)g_c2)[NB4 + j] = z;
    }
}

// ---------------------------------------------------------------------------
// Kernel 2: one full Newton-GS sweep, lane-per-chunk.
// Prologue: chunk start from prev sweep's P/T scan data.
//   global prefix through k-1 = P_{k-1} ∘ E_wp       (k-1 in same warp)
//                             = E_wp                  (k % 32 == 0; P of the
//                               previous warp's lane31 is already inside E_wp)
// Body: integrate L_CH steps (x-domain) with exact Jacobian, per lane.
// Epilogue: in-warp KS scan of the 32 affine maps; store P (per chunk) and
// T (per warp) into the write buffer.
// ---------------------------------------------------------------------------
__global__ void __launch_bounds__(32)
chunk_sweep(const float* __restrict__ Amat, const float* __restrict__ dtp,
            int first, int rd) {
    int wp = blockIdx.x;           // warp id = block id (0..NWARP-1)
    int lane = threadIdx.x;
    int k = (wp << 5) + lane;      // this lane's chunk
    const float dt = dtp[0];
    const float A00 = Amat[0], A01 = Amat[1], A02 = Amat[2];
    const float A10 = Amat[3], A11 = Amat[4], A12 = Amat[5];
    const float A20 = Amat[6], A21 = Amat[7], A22 = Amat[8];

    // ---- prologue: chunk start ----
    float st0 = 0.f, st1 = 0.f, st2 = 0.f;
    if (!first) {
        float e0, e1, e2;
        warp_excl_total(g_Tb[rd], wp, lane, e0, e1, e2);
        if (lane > 0) {            // k-1 in same warp: st = P_{k-1}(e)
            Map P = map_load(g_Pb[rd] + 12 * (k - 1));
            st0 = fmaf(P.M00, e0, fmaf(P.M01, e1, fmaf(P.M02, e2, P.v0)));
            st1 = fmaf(P.M10, e0, fmaf(P.M11, e1, fmaf(P.M12, e2, P.v1)));
            st2 = fmaf(P.M20, e0, fmaf(P.M21, e1, fmaf(P.M22, e2, P.v2)));
        } else {                   // k % 32 == 0: st = E_wp(0)  (k==0 -> 0)
            st0 = e0; st1 = e1; st2 = e2;
        }
    }

    // ---- integrate with Jacobian ----
    float x0 = st0, x1 = st1, x2 = st2;
    float J00 = 1.f, J01 = 0.f, J02 = 0.f;
    float J10 = 0.f, J11 = 1.f, J12 = 0.f;
    float J20 = 0.f, J21 = 0.f, J22 = 1.f;

    const float4* CT = g_cT + k;   // stride K_CH between steps
    float4 cb[8];
#pragma unroll
    for (int i = 0; i < 8; ++i) cb[i] = CT[i * K_CH];

#pragma unroll 1
    for (int g = 0; g < L_CH / 8; ++g) {
        bool pf = (g < L_CH / 8 - 1);
#pragma unroll
        for (int i = 0; i < 8; ++i) {
            float4 cc = cb[i];
            if (pf) cb[i] = CT[(g * 8 + i + 8) * K_CH];
            float w0 = fmaf(A00, x0, fmaf(A01, x1, fmaf(A02, x2, cc.x)));
            float w1 = fmaf(A10, x0, fmaf(A11, x1, fmaf(A12, x2, cc.y)));
            float w2 = fmaf(A20, x0, fmaf(A21, x1, fmaf(A22, x2, cc.z)));
            float t0, t1, t2;
            asm("tanh.approx.f32 %0, %1;" : "=f"(t0) : "f"(w0));
            asm("tanh.approx.f32 %0, %1;" : "=f"(t1) : "f"(w1));
            asm("tanh.approx.f32 %0, %1;" : "=f"(t2) : "f"(w2));
            x0 = fmaf(dt, t0, x0);
            x1 = fmaf(dt, t1, x1);
            x2 = fmaf(dt, t2, x2);
            float m0 = dt * t0, m1 = dt * t1, m2 = dt * t2;
            float v0 = fmaf(-m0, t0, dt);
            float v1 = fmaf(-m1, t1, dt);
            float v2 = fmaf(-m2, t2, dt);
            float P00 = fmaf(A00, J00, fmaf(A01, J10, A02 * J20));
            float P01 = fmaf(A00, J01, fmaf(A01, J11, A02 * J21));
            float P02 = fmaf(A00, J02, fmaf(A01, J12, A02 * J22));
            float P10 = fmaf(A10, J00, fmaf(A11, J10, A12 * J20));
            float P11 = fmaf(A10, J01, fmaf(A11, J11, A12 * J21));
            float P12 = fmaf(A10, J02, fmaf(A11, J12, A12 * J22));
            float P20 = fmaf(A20, J00, fmaf(A21, J10, A22 * J20));
            float P21 = fmaf(A20, J01, fmaf(A21, J11, A22 * J21));
            float P22 = fmaf(A20, J02, fmaf(A21, J12, A22 * J22));
            J00 = fmaf(v0, P00, J00); J01 = fmaf(v0, P01, J01); J02 = fmaf(v0, P02, J02);
            J10 = fmaf(v1, P10, J10); J11 = fmaf(v1, P11, J11); J12 = fmaf(v1, P12, J12);
            J20 = fmaf(v2, P20, J20); J21 = fmaf(v2, P21, J21); J22 = fmaf(v2, P22, J22);
        }
    }

    // ---- epilogue: affine map m_k = (J, g' = x - J st); in-warp KS scan ----
    Map m;
    m.M00 = J00; m.M01 = J01; m.M02 = J02;
    m.M10 = J10; m.M11 = J11; m.M12 = J12;
    m.M20 = J20; m.M21 = J21; m.M22 = J22;
    m.v0 = x0 - fmaf(J00, st0, fmaf(J01, st1, J02 * st2));
    m.v1 = x1 - fmaf(J10, st0, fmaf(J11, st1, J12 * st2));
    m.v2 = x2 - fmaf(J20, st0, fmaf(J21, st1, J22 * st2));
#pragma unroll
    for (int d = 1; d < 32; d <<= 1) {
        Map L = map_shfl_up(m, d);
        if (lane >= d) m = map_comp(m, L);
    }
    map_store(g_Pb[rd ^ 1] + 12 * k, m);
    if (lane == 31) map_store(g_Tb[rd ^ 1] + 12 * wp, m);
}

// ---------------------------------------------------------------------------
// Kernel 3: final trajectory pass. Block k recomputes its converged start
// (same prologue math incl. warp-boundary rule), lane 0 integrates & writes.
// ---------------------------------------------------------------------------
__global__ void __launch_bounds__(32)
chunk_final(const float* __restrict__ Amat, const float* __restrict__ dtp,
            float* __restrict__ memb, int rd) {
    int k = blockIdx.x;
    int lane = threadIdx.x;
    int wp = k >> 5;

    float e0, e1, e2;
    warp_excl_total(g_Tb[rd], wp, lane, e0, e1, e2);
    if (lane != 0) return;

    float st0, st1, st2;
    if (k & 31) {                  // k-1 in same warp
        Map P = map_load(g_Pb[rd] + 12 * (k - 1));
        st0 = fmaf(P.M00, e0, fmaf(P.M01, e1, fmaf(P.M02, e2, P.v0)));
        st1 = fmaf(P.M10, e0, fmaf(P.M11, e1, fmaf(P.M12, e2, P.v1)));
        st2 = fmaf(P.M20, e0, fmaf(P.M21, e1, fmaf(P.M22, e2, P.v2)));
    } else {                       // k % 32 == 0: st = E_wp(0)  (k==0 -> 0)
        st0 = e0; st1 = e1; st2 = e2;
    }

    const float dt = dtp[0];
    const float A00 = Amat[0], A01 = Amat[1], A02 = Amat[2];
    const float A10 = Amat[3], A11 = Amat[4], A12 = Amat[5];
    const float A20 = Amat[6], A21 = Amat[7], A22 = Amat[8];

    float x0 = st0, x1 = st1, x2 = st2;
    int t0i = k * L_CH;
    const float4* C0 = (const float4*)g_c0 + (t0i >> 2);
    const float4* C1 = (const float4*)g_c1 + (t0i >> 2);
    const float4* C2 = (const float4*)g_c2 + (t0i >> 2);
    float4* M0 = (float4*)memb + (t0i >> 2);
    float4* M1 = (float4*)(memb + S_LEN) + (t0i >> 2);
    float4* M2 = (float4*)(memb + 2 * S_LEN) + (t0i >> 2);

    float4 a0 = C0[0], a1 = C1[0], a2 = C2[0];
    float4 b0 = C0[1], b1 = C1[1], b2 = C2[1];

#define F_STEP(CC0, CC1, CC2, FLD)                                           \
    do {                                                                     \
        float w0 = fmaf(A00, x0, fmaf(A01, x1, fmaf(A02, x2, (CC0))));       \
        float w1 = fmaf(A10, x0, fmaf(A11, x1, fmaf(A12, x2, (CC1))));       \
        float w2 = fmaf(A20, x0, fmaf(A21, x1, fmaf(A22, x2, (CC2))));       \
        float t0v, t1v, t2v;                                                 \
        asm("tanh.approx.f32 %0, %1;" : "=f"(t0v) : "f"(w0));                \
        asm("tanh.approx.f32 %0, %1;" : "=f"(t1v) : "f"(w1));                \
        asm("tanh.approx.f32 %0, %1;" : "=f"(t2v) : "f"(w2));                \
        x0 = fmaf(dt, t0v, x0);                                              \
        x1 = fmaf(dt, t1v, x1);                                              \
        x2 = fmaf(dt, t2v, x2);                                              \
        o0.FLD = x0; o1.FLD = x1; o2.FLD = x2;                               \
    } while (0)

    for (int j = 0; j < LB4; ++j) {
        float4 n0 = C0[j + 2], n1 = C1[j + 2], n2 = C2[j + 2];
        float4 o0, o1, o2;
        F_STEP(a0.x, a1.x, a2.x, x);
        F_STEP(a0.y, a1.y, a2.y, y);
        F_STEP(a0.z, a1.z, a2.z, z);
        F_STEP(a0.w, a1.w, a2.w, w);
        M0[j] = o0; M1[j] = o1; M2[j] = o2;
        a0 = b0; a1 = b1; a2 = b2;
        b0 = n0; b1 = n1; b2 = n2;
    }
#undef F_STEP
}

// ---------------------------------------------------------------------------
// Kernel 4: pointwise MLP  out = W2 relu(W1 x + b1) + b2, warp-parallel.
// ---------------------------------------------------------------------------
__global__ void mlp_kernel(const float* __restrict__ memb,
                           const float* __restrict__ W1, const float* __restrict__ b1,
                           const float* __restrict__ W2, const float* __restrict__ b2,
                           float* __restrict__ out) {
    int warp = (blockIdx.x * blockDim.x + threadIdx.x) >> 5;
    int lane = threadIdx.x & 31;
    int tbase = warp * CHW;
    if (tbase >= S_LEN) return;

    float w1r[8][3], b1r[8], w2r[3][8];
#pragma unroll
    for (int k = 0; k < 8; ++k) {
        int h = lane * 8 + k;
        w1r[k][0] = W1[h * 3 + 0];
        w1r[k][1] = W1[h * 3 + 1];
        w1r[k][2] = W1[h * 3 + 2];
        b1r[k]    = b1[h];
        w2r[0][k] = W2[0 * HID + h];
        w2r[1][k] = W2[1 * HID + h];
        w2r[2][k] = W2[2 * HID + h];
    }
    float ob0 = b2[0], ob1 = b2[1], ob2 = b2[2];

    for (int t = tbase; t < tbase + CHW; ++t) {
        float xv0 = __ldg(&memb[t]);
        float xv1 = __ldg(&memb[S_LEN + t]);
        float xv2 = __ldg(&memb[2 * S_LEN + t]);
        float a0 = 0.f, a1 = 0.f, a2 = 0.f;
#pragma unroll
        for (int k = 0; k < 8; ++k) {
            float hv = fmaf(w1r[k][2], xv2,
                       fmaf(w1r[k][1], xv1,
                       fmaf(w1r[k][0], xv0, b1r[k])));
            hv = fmaxf(hv, 0.f);
            a0 = fmaf(w2r[0][k], hv, a0);
            a1 = fmaf(w2r[1][k], hv, a1);
            a2 = fmaf(w2r[2][k], hv, a2);
        }
#pragma unroll
        for (int off = 16; off > 0; off >>= 1) {
            a0 += __shfl_xor_sync(0xffffffffu, a0, off);
            a1 += __shfl_xor_sync(0xffffffffu, a1, off);
            a2 += __shfl_xor_sync(0xffffffffu, a2, off);
        }
        if (lane == 0) {
            out[t]              = a0 + ob0;
            out[S_LEN + t]      = a1 + ob1;
            out[2 * S_LEN + t]  = a2 + ob2;
        }
    }
}

// ---------------------------------------------------------------------------
// Launch: inputs: u, dt, A, B, bA, W1, b1, W2, b2.
// d_out: outputs[3*S] then membrane_potentials[3*S].
// ---------------------------------------------------------------------------
extern "C" void kernel_launch(void* const* d_in, const int* in_sizes, int n_in,
                              void* d_out, int out_size) {
    const float* u  = (const float*)d_in[0];
    const float* dt = (const float*)d_in[1];
    const float* A  = (const float*)d_in[2];
    const float* B  = (const float*)d_in[3];
    const float* bA = (const float*)d_in[4];
    const float* W1 = (const float*)d_in[5];
    const float* b1 = (const float*)d_in[6];
    const float* W2 = (const float*)d_in[7];
    const float* b2 = (const float*)d_in[8];
    float* out  = (float*)d_out;
    float* memb = out + 3 * S_LEN;

    precompute_c<<<NB4 / 256, 256>>>(u, B, bA);
    for (int s = 0; s < NSWEEP; ++s) {
        // sweep s reads buffer (s&1), writes (s&1)^1
        chunk_sweep<<<NWARP, 32>>>(A, dt, (s == 0) ? 1 : 0, s & 1);
    }
    chunk_final<<<K_CH, 32>>>(A, dt, memb, NSWEEP & 1);
    mlp_kernel<<<(S_LEN / CHW) / 8, 256>>>(memb, W1, b1, W2, b2, out);
}

// round 17
// speedup vs baseline: 95.1481x; 1.0616x over previous
#include <cuda_runtime.h>

#define S_LEN  262144
#define NB4    (S_LEN / 4)       // 65536 float4 time-chunks
#define K_CH   4096              // number of time chunks
#define L_CH   (S_LEN / K_CH)    // 64 steps per chunk
#define LB4    (L_CH / 4)        // 16 float4 iterations per chunk (final pass)
#define NWARP  (K_CH / 32)       // 128 warps, one per sweep block
#define HID    256
#define CHW    32                // timesteps per warp in MLP kernel
#define NSWEEP 6                 // full Newton-GS sweeps

// c_t = B u_t + bA: time-major (for final pass) + chunk-major float4 (for sweeps)
__device__ __align__(16) float  g_c0[S_LEN + 8];
__device__ __align__(16) float  g_c1[S_LEN + 8];
__device__ __align__(16) float  g_c2[S_LEN + 8];
__device__ __align__(16) float4 g_cT[S_LEN];          // [s*K_CH + k] = (c0,c1,c2,0)

// Ping-pong affine-map state: per-chunk within-warp inclusive prefixes P and
// per-warp totals T. 12 floats per record: M00..M22 row-major, v0..v2.
__device__ __align__(16) float g_Pb[2][12 * K_CH];
__device__ __align__(16) float g_Tb[2][12 * NWARP];

// ---------------------------------------------------------------------------
// Affine map helpers (3x3 matrix + vector), all in registers.
// ---------------------------------------------------------------------------
struct Map {
    float M00, M01, M02, M10, M11, M12, M20, M21, M22, v0, v1, v2;
};

__device__ __forceinline__ Map map_identity() {
    Map r;
    r.M00 = 1.f; r.M01 = 0.f; r.M02 = 0.f;
    r.M10 = 0.f; r.M11 = 1.f; r.M12 = 0.f;
    r.M20 = 0.f; r.M21 = 0.f; r.M22 = 1.f;
    r.v0 = 0.f; r.v1 = 0.f; r.v2 = 0.f;
    return r;
}

// (s ∘ l): apply l first, then s.  M = Ms*Ml,  v = Ms*vl + vs
__device__ __forceinline__ Map map_comp(const Map& s, const Map& l) {
    Map r;
    r.M00 = fmaf(s.M00, l.M00, fmaf(s.M01, l.M10, s.M02 * l.M20));
    r.M01 = fmaf(s.M00, l.M01, fmaf(s.M01, l.M11, s.M02 * l.M21));
    r.M02 = fmaf(s.M00, l.M02, fmaf(s.M01, l.M12, s.M02 * l.M22));
    r.M10 = fmaf(s.M10, l.M00, fmaf(s.M11, l.M10, s.M12 * l.M20));
    r.M11 = fmaf(s.M10, l.M01, fmaf(s.M11, l.M11, s.M12 * l.M21));
    r.M12 = fmaf(s.M10, l.M02, fmaf(s.M11, l.M12, s.M12 * l.M22));
    r.M20 = fmaf(s.M20, l.M00, fmaf(s.M21, l.M10, s.M22 * l.M20));
    r.M21 = fmaf(s.M20, l.M01, fmaf(s.M21, l.M11, s.M22 * l.M21));
    r.M22 = fmaf(s.M20, l.M02, fmaf(s.M21, l.M12, s.M22 * l.M22));
    r.v0  = fmaf(s.M00, l.v0, fmaf(s.M01, l.v1, fmaf(s.M02, l.v2, s.v0)));
    r.v1  = fmaf(s.M10, l.v0, fmaf(s.M11, l.v1, fmaf(s.M12, l.v2, s.v1)));
    r.v2  = fmaf(s.M20, l.v0, fmaf(s.M21, l.v1, fmaf(s.M22, l.v2, s.v2)));
    return r;
}

__device__ __forceinline__ Map map_shfl_up(const Map& m, int d) {
    Map r;
    r.M00 = __shfl_up_sync(0xffffffffu, m.M00, d);
    r.M01 = __shfl_up_sync(0xffffffffu, m.M01, d);
    r.M02 = __shfl_up_sync(0xffffffffu, m.M02, d);
    r.M10 = __shfl_up_sync(0xffffffffu, m.M10, d);
    r.M11 = __shfl_up_sync(0xffffffffu, m.M11, d);
    r.M12 = __shfl_up_sync(0xffffffffu, m.M12, d);
    r.M20 = __shfl_up_sync(0xffffffffu, m.M20, d);
    r.M21 = __shfl_up_sync(0xffffffffu, m.M21, d);
    r.M22 = __shfl_up_sync(0xffffffffu, m.M22, d);
    r.v0  = __shfl_up_sync(0xffffffffu, m.v0, d);
    r.v1  = __shfl_up_sync(0xffffffffu, m.v1, d);
    r.v2  = __shfl_up_sync(0xffffffffu, m.v2, d);
    return r;
}

__device__ __forceinline__ Map map_load(const float* p) {
    const float4* q = (const float4*)p;
    float4 a = q[0], b = q[1], c = q[2];
    Map r;
    r.M00 = a.x; r.M01 = a.y; r.M02 = a.z; r.M10 = a.w;
    r.M11 = b.x; r.M12 = b.y; r.M20 = b.z; r.M21 = b.w;
    r.M22 = c.x; r.v0 = c.y; r.v1 = c.z; r.v2 = c.w;
    return r;
}

__device__ __forceinline__ void map_store(float* p, const Map& m) {
    float4* q = (float4*)p;
    q[0] = make_float4(m.M00, m.M01, m.M02, m.M10);
    q[1] = make_float4(m.M11, m.M12, m.M20, m.M21);
    q[2] = make_float4(m.M22, m.v0, m.v1, m.v2);
}

// Warp-collective: e = (compose of totals T_0..T_{w-1}, in order)(0).
// Lanes load 4 totals each (coalesced), predicate-compose, KS-scan, bcast.
__device__ __forceinline__ void warp_excl_total(const float* Tr, int w, int lane,
                                                float& e0, float& e1, float& e2) {
    Map C = map_identity();
#pragma unroll
    for (int i = 0; i < 4; ++i) {
        int j = (lane << 2) + i;
        Map T = map_load(Tr + 12 * j);
        if (j < w) C = map_comp(T, C);
    }
#pragma unroll
    for (int d = 1; d < 32; d <<= 1) {
        Map L = map_shfl_up(C, d);
        if (lane >= d) C = map_comp(C, L);
    }
    e0 = __shfl_sync(0xffffffffu, C.v0, 31);
    e1 = __shfl_sync(0xffffffffu, C.v1, 31);
    e2 = __shfl_sync(0xffffffffu, C.v2, 31);
}

// ---------------------------------------------------------------------------
// Kernel 1: c_t = B @ u_t + bA: time-major float arrays + chunk-major float4.
// ---------------------------------------------------------------------------
__global__ void precompute_c(const float* __restrict__ u,
                             const float* __restrict__ B,
                             const float* __restrict__ bA) {
    int j = blockIdx.x * blockDim.x + threadIdx.x;   // float4 time index
    if (j >= NB4) return;
    const float4* u0 = (const float4*)u;
    const float4* u1 = (const float4*)(u + S_LEN);
    const float4* u2 = (const float4*)(u + 2 * S_LEN);
    float4 a = u0[j], b = u1[j], c = u2[j];

    float B00 = B[0], B01 = B[1], B02 = B[2];
    float B10 = B[3], B11 = B[4], B12 = B[5];
    float B20 = B[6], B21 = B[7], B22 = B[8];
    float A0 = bA[0], A1 = bA[1], A2 = bA[2];

    float4 r0, r1, r2;
    r0.x = fmaf(B00, a.x, fmaf(B01, b.x, fmaf(B02, c.x, A0)));
    r0.y = fmaf(B00, a.y, fmaf(B01, b.y, fmaf(B02, c.y, A0)));
    r0.z = fmaf(B00, a.z, fmaf(B01, b.z, fmaf(B02, c.z, A0)));
    r0.w = fmaf(B00, a.w, fmaf(B01, b.w, fmaf(B02, c.w, A0)));

    r1.x = fmaf(B10, a.x, fmaf(B11, b.x, fmaf(B12, c.x, A1)));
    r1.y = fmaf(B10, a.y, fmaf(B11, b.y, fmaf(B12, c.y, A1)));
    r1.z = fmaf(B10, a.z, fmaf(B11, b.z, fmaf(B12, c.z, A1)));
    r1.w = fmaf(B10, a.w, fmaf(B11, b.w, fmaf(B12, c.w, A1)));

    r2.x = fmaf(B20, a.x, fmaf(B21, b.x, fmaf(B22, c.x, A2)));
    r2.y = fmaf(B20, a.y, fmaf(B21, b.y, fmaf(B22, c.y, A2)));
    r2.z = fmaf(B20, a.z, fmaf(B21, b.z, fmaf(B22, c.z, A2)));
    r2.w = fmaf(B20, a.w, fmaf(B21, b.w, fmaf(B22, c.w, A2)));

    ((float4*)g_c0)[j] = r0;
    ((float4*)g_c1)[j] = r1;
    ((float4*)g_c2)[j] = r2;

    // chunk-major transpose: t = 4j..4j+3, all in same chunk (64 | alignment)
    int t = 4 * j;
    int k = t >> 6;        // chunk index (L_CH = 64)
    int s = t & 63;        // step within chunk
    g_cT[(s + 0) * K_CH + k] = make_float4(r0.x, r1.x, r2.x, 0.f);
    g_cT[(s + 1) * K_CH + k] = make_float4(r0.y, r1.y, r2.y, 0.f);
    g_cT[(s + 2) * K_CH + k] = make_float4(r0.z, r1.z, r2.z, 0.f);
    g_cT[(s + 3) * K_CH + k] = make_float4(r0.w, r1.w, r2.w, 0.f);

    if (j < 2) {   // pad for the final pass's float4 prefetch overrun
        float4 z = make_float4(0.f, 0.f, 0.f, 0.f);
        ((float4*)g_c0)[NB4 + j] = z;
        ((float4*)g_c1)[NB4 + j] = z;
        ((float4*)g_c2)[NB4 + j] = z;
    }
}

// ---------------------------------------------------------------------------
// Kernel 2: one full Newton-GS sweep, lane-per-chunk.
// __launch_bounds__(32, 1): minBlocks=1 lifts the ptxas register cap to 255
// (default heuristic capped at 64 and SPILLED the cb[8]/J state to local —
// measured 19.8us instead of ~4us in R16).
// ---------------------------------------------------------------------------
__global__ void __launch_bounds__(32, 1)
chunk_sweep(const float* __restrict__ Amat, const float* __restrict__ dtp,
            int first, int rd) {
    int wp = blockIdx.x;           // warp id = block id (0..NWARP-1)
    int lane = threadIdx.x;
    int k = (wp << 5) + lane;      // this lane's chunk
    const float dt = dtp[0];
    const float A00 = Amat[0], A01 = Amat[1], A02 = Amat[2];
    const float A10 = Amat[3], A11 = Amat[4], A12 = Amat[5];
    const float A20 = Amat[6], A21 = Amat[7], A22 = Amat[8];

    // ---- prologue: chunk start ----
    float st0 = 0.f, st1 = 0.f, st2 = 0.f;
    if (!first) {
        float e0, e1, e2;
        warp_excl_total(g_Tb[rd], wp, lane, e0, e1, e2);
        if (lane > 0) {            // k-1 in same warp: st = P_{k-1}(e)
            Map P = map_load(g_Pb[rd] + 12 * (k - 1));
            st0 = fmaf(P.M00, e0, fmaf(P.M01, e1, fmaf(P.M02, e2, P.v0)));
            st1 = fmaf(P.M10, e0, fmaf(P.M11, e1, fmaf(P.M12, e2, P.v1)));
            st2 = fmaf(P.M20, e0, fmaf(P.M21, e1, fmaf(P.M22, e2, P.v2)));
        } else {                   // k % 32 == 0: st = E_wp(0)  (k==0 -> 0)
            st0 = e0; st1 = e1; st2 = e2;
        }
    }

    // ---- integrate with Jacobian ----
    float x0 = st0, x1 = st1, x2 = st2;
    float J00 = 1.f, J01 = 0.f, J02 = 0.f;
    float J10 = 0.f, J11 = 1.f, J12 = 0.f;
    float J20 = 0.f, J21 = 0.f, J22 = 1.f;

    const float4* CT = g_cT + k;   // stride K_CH between steps
    float4 cb[8];
#pragma unroll
    for (int i = 0; i < 8; ++i) cb[i] = CT[i * K_CH];

#pragma unroll 1
    for (int g = 0; g < L_CH / 8; ++g) {
        bool pf = (g < L_CH / 8 - 1);
#pragma unroll
        for (int i = 0; i < 8; ++i) {
            float4 cc = cb[i];
            if (pf) cb[i] = CT[(g * 8 + i + 8) * K_CH];
            float w0 = fmaf(A00, x0, fmaf(A01, x1, fmaf(A02, x2, cc.x)));
            float w1 = fmaf(A10, x0, fmaf(A11, x1, fmaf(A12, x2, cc.y)));
            float w2 = fmaf(A20, x0, fmaf(A21, x1, fmaf(A22, x2, cc.z)));
            float t0, t1, t2;
            asm("tanh.approx.f32 %0, %1;" : "=f"(t0) : "f"(w0));
            asm("tanh.approx.f32 %0, %1;" : "=f"(t1) : "f"(w1));
            asm("tanh.approx.f32 %0, %1;" : "=f"(t2) : "f"(w2));
            x0 = fmaf(dt, t0, x0);
            x1 = fmaf(dt, t1, x1);
            x2 = fmaf(dt, t2, x2);
            float m0 = dt * t0, m1 = dt * t1, m2 = dt * t2;
            float v0 = fmaf(-m0, t0, dt);
            float v1 = fmaf(-m1, t1, dt);
            float v2 = fmaf(-m2, t2, dt);
            float P00 = fmaf(A00, J00, fmaf(A01, J10, A02 * J20));
            float P01 = fmaf(A00, J01, fmaf(A01, J11, A02 * J21));
            float P02 = fmaf(A00, J02, fmaf(A01, J12, A02 * J22));
            float P10 = fmaf(A10, J00, fmaf(A11, J10, A12 * J20));
            float P11 = fmaf(A10, J01, fmaf(A11, J11, A12 * J21));
            float P12 = fmaf(A10, J02, fmaf(A11, J12, A12 * J22));
            float P20 = fmaf(A20, J00, fmaf(A21, J10, A22 * J20));
            float P21 = fmaf(A20, J01, fmaf(A21, J11, A22 * J21));
            float P22 = fmaf(A20, J02, fmaf(A21, J12, A22 * J22));
            J00 = fmaf(v0, P00, J00); J01 = fmaf(v0, P01, J01); J02 = fmaf(v0, P02, J02);
            J10 = fmaf(v1, P10, J10); J11 = fmaf(v1, P11, J11); J12 = fmaf(v1, P12, J12);
            J20 = fmaf(v2, P20, J20); J21 = fmaf(v2, P21, J21); J22 = fmaf(v2, P22, J22);
        }
    }

    // ---- epilogue: affine map m_k = (J, g' = x - J st); in-warp KS scan ----
    Map m;
    m.M00 = J00; m.M01 = J01; m.M02 = J02;
    m.M10 = J10; m.M11 = J11; m.M12 = J12;
    m.M20 = J20; m.M21 = J21; m.M22 = J22;
    m.v0 = x0 - fmaf(J00, st0, fmaf(J01, st1, J02 * st2));
    m.v1 = x1 - fmaf(J10, st0, fmaf(J11, st1, J12 * st2));
    m.v2 = x2 - fmaf(J20, st0, fmaf(J21, st1, J22 * st2));
#pragma unroll
    for (int d = 1; d < 32; d <<= 1) {
        Map L = map_shfl_up(m, d);
        if (lane >= d) m = map_comp(m, L);
    }
    map_store(g_Pb[rd ^ 1] + 12 * k, m);
    if (lane == 31) map_store(g_Tb[rd ^ 1] + 12 * wp, m);
}

// ---------------------------------------------------------------------------
// Kernel 3: final trajectory pass. Block k recomputes its converged start
// (same prologue math incl. warp-boundary rule), lane 0 integrates & writes.
// ---------------------------------------------------------------------------
__global__ void __launch_bounds__(32, 1)
chunk_final(const float* __restrict__ Amat, const float* __restrict__ dtp,
            float* __restrict__ memb, int rd) {
    int k = blockIdx.x;
    int lane = threadIdx.x;
    int wp = k >> 5;

    float e0, e1, e2;
    warp_excl_total(g_Tb[rd], wp, lane, e0, e1, e2);
    if (lane != 0) return;

    float st0, st1, st2;
    if (k & 31) {                  // k-1 in same warp
        Map P = map_load(g_Pb[rd] + 12 * (k - 1));
        st0 = fmaf(P.M00, e0, fmaf(P.M01, e1, fmaf(P.M02, e2, P.v0)));
        st1 = fmaf(P.M10, e0, fmaf(P.M11, e1, fmaf(P.M12, e2, P.v1)));
        st2 = fmaf(P.M20, e0, fmaf(P.M21, e1, fmaf(P.M22, e2, P.v2)));
    } else {                       // k % 32 == 0: st = E_wp(0)  (k==0 -> 0)
        st0 = e0; st1 = e1; st2 = e2;
    }

    const float dt = dtp[0];
    const float A00 = Amat[0], A01 = Amat[1], A02 = Amat[2];
    const float A10 = Amat[3], A11 = Amat[4], A12 = Amat[5];
    const float A20 = Amat[6], A21 = Amat[7], A22 = Amat[8];

    float x0 = st0, x1 = st1, x2 = st2;
    int t0i = k * L_CH;
    const float4* C0 = (const float4*)g_c0 + (t0i >> 2);
    const float4* C1 = (const float4*)g_c1 + (t0i >> 2);
    const float4* C2 = (const float4*)g_c2 + (t0i >> 2);
    float4* M0 = (float4*)memb + (t0i >> 2);
    float4* M1 = (float4*)(memb + S_LEN) + (t0i >> 2);
    float4* M2 = (float4*)(memb + 2 * S_LEN) + (t0i >> 2);

    float4 a0 = C0[0], a1 = C1[0], a2 = C2[0];
    float4 b0 = C0[1], b1 = C1[1], b2 = C2[1];

#define F_STEP(CC0, CC1, CC2, FLD)                                           \
    do {                                                                     \
        float w0 = fmaf(A00, x0, fmaf(A01, x1, fmaf(A02, x2, (CC0))));       \
        float w1 = fmaf(A10, x0, fmaf(A11, x1, fmaf(A12, x2, (CC1))));       \
        float w2 = fmaf(A20, x0, fmaf(A21, x1, fmaf(A22, x2, (CC2))));       \
        float t0v, t1v, t2v;                                                 \
        asm("tanh.approx.f32 %0, %1;" : "=f"(t0v) : "f"(w0));                \
        asm("tanh.approx.f32 %0, %1;" : "=f"(t1v) : "f"(w1));                \
        asm("tanh.approx.f32 %0, %1;" : "=f"(t2v) : "f"(w2));                \
        x0 = fmaf(dt, t0v, x0);                                              \
        x1 = fmaf(dt, t1v, x1);                                              \
        x2 = fmaf(dt, t2v, x2);                                              \
        o0.FLD = x0; o1.FLD = x1; o2.FLD = x2;                               \
    } while (0)

    for (int j = 0; j < LB4; ++j) {
        float4 n0 = C0[j + 2], n1 = C1[j + 2], n2 = C2[j + 2];
        float4 o0, o1, o2;
        F_STEP(a0.x, a1.x, a2.x, x);
        F_STEP(a0.y, a1.y, a2.y, y);
        F_STEP(a0.z, a1.z, a2.z, z);
        F_STEP(a0.w, a1.w, a2.w, w);
        M0[j] = o0; M1[j] = o1; M2[j] = o2;
        a0 = b0; a1 = b1; a2 = b2;
        b0 = n0; b1 = n1; b2 = n2;
    }
#undef F_STEP
}

// ---------------------------------------------------------------------------
// Kernel 4: pointwise MLP  out = W2 relu(W1 x + b1) + b2, warp-parallel.
// ---------------------------------------------------------------------------
__global__ void mlp_kernel(const float* __restrict__ memb,
                           const float* __restrict__ W1, const float* __restrict__ b1,
                           const float* __restrict__ W2, const float* __restrict__ b2,
                           float* __restrict__ out) {
    int warp = (blockIdx.x * blockDim.x + threadIdx.x) >> 5;
    int lane = threadIdx.x & 31;
    int tbase = warp * CHW;
    if (tbase >= S_LEN) return;

    float w1r[8][3], b1r[8], w2r[3][8];
#pragma unroll
    for (int k = 0; k < 8; ++k) {
        int h = lane * 8 + k;
        w1r[k][0] = W1[h * 3 + 0];
        w1r[k][1] = W1[h * 3 + 1];
        w1r[k][2] = W1[h * 3 + 2];
        b1r[k]    = b1[h];
        w2r[0][k] = W2[0 * HID + h];
        w2r[1][k] = W2[1 * HID + h];
        w2r[2][k] = W2[2 * HID + h];
    }
    float ob0 = b2[0], ob1 = b2[1], ob2 = b2[2];

    for (int t = tbase; t < tbase + CHW; ++t) {
        float xv0 = __ldg(&memb[t]);
        float xv1 = __ldg(&memb[S_LEN + t]);
        float xv2 = __ldg(&memb[2 * S_LEN + t]);
        float a0 = 0.f, a1 = 0.f, a2 = 0.f;
#pragma unroll
        for (int k = 0; k < 8; ++k) {
            float hv = fmaf(w1r[k][2], xv2,
                       fmaf(w1r[k][1], xv1,
                       fmaf(w1r[k][0], xv0, b1r[k])));
            hv = fmaxf(hv, 0.f);
            a0 = fmaf(w2r[0][k], hv, a0);
            a1 = fmaf(w2r[1][k], hv, a1);
            a2 = fmaf(w2r[2][k], hv, a2);
        }
#pragma unroll
        for (int off = 16; off > 0; off >>= 1) {
            a0 += __shfl_xor_sync(0xffffffffu, a0, off);
            a1 += __shfl_xor_sync(0xffffffffu, a1, off);
            a2 += __shfl_xor_sync(0xffffffffu, a2, off);
        }
        if (lane == 0) {
            out[t]              = a0 + ob0;
            out[S_LEN + t]      = a1 + ob1;
            out[2 * S_LEN + t]  = a2 + ob2;
        }
    }
}

// ---------------------------------------------------------------------------
// Launch: inputs: u, dt, A, B, bA, W1, b1, W2, b2.
// d_out: outputs[3*S] then membrane_potentials[3*S].
// ---------------------------------------------------------------------------
extern "C" void kernel_launch(void* const* d_in, const int* in_sizes, int n_in,
                              void* d_out, int out_size) {
    const float* u  = (const float*)d_in[0];
    const float* dt = (const float*)d_in[1];
    const float* A  = (const float*)d_in[2];
    const float* B  = (const float*)d_in[3];
    const float* bA = (const float*)d_in[4];
    const float* W1 = (const float*)d_in[5];
    const float* b1 = (const float*)d_in[6];
    const float* W2 = (const float*)d_in[7];
    const float* b2 = (const float*)d_in[8];
    float* out  = (float*)d_out;
    float* memb = out + 3 * S_LEN;

    precompute_c<<<NB4 / 256, 256>>>(u, B, bA);
    for (int s = 0; s < NSWEEP; ++s) {
        // sweep s reads buffer (s&1), writes (s&1)^1
        chunk_sweep<<<NWARP, 32>>>(A, dt, (s == 0) ? 1 : 0, s & 1);
    }
    chunk_final<<<K_CH, 32>>>(A, dt, memb, NSWEEP & 1);
    mlp_kernel<<<(S_LEN / CHW) / 8, 256>>>(memb, W1, b1, W2, b2, out);
}